// round 1
// baseline (speedup 1.0000x reference)
#include <cuda_runtime.h>
#include <cstdint>

#define DIMK 32
#define NBLK 6
#define NB   16
#define NN   256

// ---------------- precomputed per-(block,batch) fused biases ----------------
__device__ float d_fbias[NBLK * NB * DIMK];
__device__ float d_gbias[NBLK * NB * DIMK];

// ---------------- f32x2 helpers (Blackwell packed fp32) ----------------
__device__ __forceinline__ unsigned long long fma2(unsigned long long a,
                                                   unsigned long long b,
                                                   unsigned long long c) {
    unsigned long long d;
    asm("fma.rn.f32x2 %0, %1, %2, %3;" : "=l"(d) : "l"(a), "l"(b), "l"(c));
    return d;
}
__device__ __forceinline__ unsigned long long pack2(float lo, float hi) {
    unsigned long long r;
    asm("mov.b64 %0, {%1, %2};" : "=l"(r) : "f"(lo), "f"(hi));
    return r;
}
__device__ __forceinline__ void unpack2(unsigned long long v, float& lo, float& hi) {
    asm("mov.b64 {%0, %1}, %2;" : "=f"(lo), "=f"(hi) : "l"(v));
}

// ---------------- precompute kernel: ex/et MLPs + fused biases ----------------
__global__ void precompute_kernel(
    const float* __restrict__ x_params,  // (B,16)
    const float* __restrict__ t_params,  // (B,8)
    const float* __restrict__ xW1, const float* __restrict__ xb1,   // (16,32),(32)
    const float* __restrict__ xW2, const float* __restrict__ xb2,   // (32,32),(32)
    const float* __restrict__ tW1, const float* __restrict__ tb1,   // (8,32),(32)
    const float* __restrict__ tW2, const float* __restrict__ tb2,   // (32,32),(32)
    const float* __restrict__ h0,  const float* __restrict__ gh0,   // (32),(32)
    const float* __restrict__ f_Wh, const float* __restrict__ f_bh, // (6,32,32),(6,32)
    const float* __restrict__ f_Wz, const float* __restrict__ f_bz, // (6,34,32),(6,32)
    const float* __restrict__ g_Wh, const float* __restrict__ g_bh, // (6,32,32),(6,32)
    const float* __restrict__ g_Wz, const float* __restrict__ g_bz) // (6,64,32),(6,32)
{
    __shared__ float s1x[NB][DIMK], s1t[NB][DIMK], ex[NB][DIMK], et[NB][DIMK];
    int t = threadIdx.x;  // 512 threads == NB*DIMK
    {
        int b = t / DIMK, k = t % DIMK;
        float a = xb1[k];
        for (int p = 0; p < 16; p++) a += x_params[b * 16 + p] * xW1[p * DIMK + k];
        s1x[b][k] = sinf(a);
        float c = tb1[k];
        for (int p = 0; p < 8; p++) c += t_params[b * 8 + p] * tW1[p * DIMK + k];
        s1t[b][k] = sinf(c);
    }
    __syncthreads();
    {
        int b = t / DIMK, k = t % DIMK;
        float a = xb2[k], c = tb2[k];
        for (int m = 0; m < DIMK; m++) {
            a += s1x[b][m] * xW2[m * DIMK + k];
            c += s1t[b][m] * tW2[m * DIMK + k];
        }
        ex[b][k] = a;
        et[b][k] = c;
    }
    __syncthreads();
    // fused biases: NBLK*NB*DIMK = 3072 items
    for (int idx = t; idx < NBLK * NB * DIMK; idx += blockDim.x) {
        int blk = idx / (NB * DIMK);
        int b   = (idx / DIMK) % NB;
        int k   = idx % DIMK;
        // f: bh + bz + et @ f_Wz[2:34]  (+ h0 @ f_Wh for block 0)
        float fa = f_bh[blk * DIMK + k] + f_bz[blk * DIMK + k];
        for (int m = 0; m < DIMK; m++)
            fa += et[b][m] * f_Wz[(blk * 34 + 2 + m) * DIMK + k];
        if (blk == 0)
            for (int m = 0; m < DIMK; m++)
                fa += h0[m] * f_Wh[m * DIMK + k];
        d_fbias[idx] = fa;
        // g: bh + bz + ex @ g_Wz[32:64]  (+ gh0 @ g_Wh for block 0)
        float ga = g_bh[blk * DIMK + k] + g_bz[blk * DIMK + k];
        for (int m = 0; m < DIMK; m++)
            ga += ex[b][m] * g_Wz[(blk * 64 + 32 + m) * DIMK + k];
        if (blk == 0)
            for (int m = 0; m < DIMK; m++)
                ga += gh0[m] * g_Wh[m * DIMK + k];
        d_gbias[idx] = ga;
    }
}

// ---------------- smem layout (float offsets) ----------------
#define OFF_FW  0        // f_Wh  [blk][m][k]   6*32*32 = 6144
#define OFF_GW  6144     // [g_Wh ; g_Wz[:32]]  [blk][m0..63][k] = 12288
#define OFF_WZ0 18432    // f_Wz row0  [blk][k] 192
#define OFF_WZ1 18624    // f_Wz row1  192
#define OFF_FB  18816    // fbias[blk][k] for this batch, 192
#define OFF_GB  19008    // gbias, 192
#define OFF_DW  19200    // d_W, 32
#define OFF_SH  19232    // per-thread h spill [m][tid] 32*256 = 8192
#define SMEM_FLOATS 27424
#define SMEM_BYTES  (SMEM_FLOATS * 4)

__global__ void __launch_bounds__(256, 2) main_kernel(
    const float* __restrict__ coords,  // (B,N,2)
    const float* __restrict__ f_Wh,    // (6,32,32)
    const float* __restrict__ f_Wz,    // (6,34,32)
    const float* __restrict__ g_Wh,    // (6,32,32)
    const float* __restrict__ g_Wz,    // (6,64,32)
    const float* __restrict__ d_W,     // (32,1)
    const float* __restrict__ d_b,     // (1)
    float* __restrict__ out)           // (B,N,N)
{
    extern __shared__ float sm[];
    const int tid = threadIdx.x;
    const int blkid = blockIdx.x;
    const int b = blkid >> 8;
    const int i = blkid & 255;

    // ---- cooperative smem staging ----
    for (int idx = tid; idx < 6144; idx += 256) sm[OFF_FW + idx] = f_Wh[idx];
    for (int idx = tid; idx < 12288; idx += 256) {
        int blk = idx >> 11;
        int rem = idx & 2047;
        int m = rem >> 5;
        int k = rem & 31;
        sm[OFF_GW + idx] = (m < 32) ? g_Wh[(blk << 10) + (m << 5) + k]
                                    : g_Wz[(blk << 11) + ((m - 32) << 5) + k];
    }
    for (int idx = tid; idx < NBLK * DIMK; idx += 256) {
        int blk = idx >> 5;
        int k = idx & 31;
        sm[OFF_WZ0 + idx] = f_Wz[(blk * 34 + 0) * DIMK + k];
        sm[OFF_WZ1 + idx] = f_Wz[(blk * 34 + 1) * DIMK + k];
        sm[OFF_FB + idx] = d_fbias[(blk * NB + b) * DIMK + k];
        sm[OFF_GB + idx] = d_gbias[(blk * NB + b) * DIMK + k];
    }
    if (tid < 32) sm[OFF_DW + tid] = d_W[tid];
    __syncthreads();

    const float x = coords[(b * NN + tid) * 2 + 0];  // x_j, j = tid
    const float t = coords[(b * NN + i) * 2 + 1];    // t_i
    const unsigned long long x2 = pack2(x, x);
    const unsigned long long t2 = pack2(t, t);

    float* shp = sm + OFF_SH + tid;  // per-thread h column
    unsigned long long acc[16];

    // ================= f chain =================
#pragma unroll 1
    for (int blk = 0; blk < NBLK; blk++) {
        const unsigned long long* fbp = (const unsigned long long*)(sm + OFF_FB + blk * 32);
        const unsigned long long* z0p = (const unsigned long long*)(sm + OFF_WZ0 + blk * 32);
        const unsigned long long* z1p = (const unsigned long long*)(sm + OFF_WZ1 + blk * 32);
#pragma unroll
        for (int p = 0; p < 16; p++) {
            unsigned long long a = fbp[p];
            a = fma2(x2, z0p[p], a);
            a = fma2(t2, z1p[p], a);
            acc[p] = a;
        }
        if (blk > 0) {
            const float* W = sm + OFF_FW + blk * 1024;
#pragma unroll 4
            for (int m = 0; m < 32; m++) {
                float hv = shp[m * 256];
                unsigned long long a = pack2(hv, hv);
                const ulonglong2* wr = (const ulonglong2*)(W + m * 32);
#pragma unroll
                for (int q = 0; q < 8; q++) {
                    ulonglong2 w = wr[q];
                    acc[2 * q]     = fma2(a, w.x, acc[2 * q]);
                    acc[2 * q + 1] = fma2(a, w.y, acc[2 * q + 1]);
                }
            }
        }
#pragma unroll
        for (int p = 0; p < 16; p++) {
            float lo, hi;
            unpack2(acc[p], lo, hi);
            shp[(2 * p) * 256]     = __sinf(lo);
            shp[(2 * p + 1) * 256] = __sinf(hi);
        }
    }

    // ================= g chain =================
    unsigned long long ghd[32];  // gh duplicated {g,g} per component
#pragma unroll 1
    for (int blk = 0; blk < NBLK; blk++) {
        const unsigned long long* gbp = (const unsigned long long*)(sm + OFF_GB + blk * 32);
#pragma unroll
        for (int p = 0; p < 16; p++) acc[p] = gbp[p];

        const float* W = sm + OFF_GW + blk * 2048;
        if (blk > 0) {
#pragma unroll
            for (int m = 0; m < 32; m++) {
                const ulonglong2* wr = (const ulonglong2*)(W + m * 32);
                unsigned long long a = ghd[m];
#pragma unroll
                for (int q = 0; q < 8; q++) {
                    ulonglong2 w = wr[q];
                    acc[2 * q]     = fma2(a, w.x, acc[2 * q]);
                    acc[2 * q + 1] = fma2(a, w.y, acc[2 * q + 1]);
                }
            }
        }
        const float* Wz = W + 1024;  // h-part rows
#pragma unroll 4
        for (int m = 0; m < 32; m++) {
            float hv = shp[m * 256];
            unsigned long long a = pack2(hv, hv);
            const ulonglong2* wr = (const ulonglong2*)(Wz + m * 32);
#pragma unroll
            for (int q = 0; q < 8; q++) {
                ulonglong2 w = wr[q];
                acc[2 * q]     = fma2(a, w.x, acc[2 * q]);
                acc[2 * q + 1] = fma2(a, w.y, acc[2 * q + 1]);
            }
        }
#pragma unroll
        for (int p = 0; p < 16; p++) {
            float lo, hi;
            unpack2(acc[p], lo, hi);
            float slo = __sinf(lo), shi = __sinf(hi);
            ghd[2 * p]     = pack2(slo, slo);
            ghd[2 * p + 1] = pack2(shi, shi);
        }
    }

    // ================= decode =================
    float u = d_b[0];
    const float* dW = sm + OFF_DW;
#pragma unroll
    for (int m = 0; m < 32; m++) {
        float g, gdummy;
        unpack2(ghd[m], g, gdummy);
        u = fmaf(g, dW[m], u);
    }
    out[blkid * 256 + tid] = u;
}

// ---------------- launch ----------------
extern "C" void kernel_launch(void* const* d_in, const int* in_sizes, int n_in,
                              void* d_out, int out_size) {
    const float* coords   = (const float*)d_in[0];
    const float* x_params = (const float*)d_in[1];
    const float* t_params = (const float*)d_in[2];
    const float* xW1 = (const float*)d_in[3];
    const float* xb1 = (const float*)d_in[4];
    const float* xW2 = (const float*)d_in[5];
    const float* xb2 = (const float*)d_in[6];
    const float* tW1 = (const float*)d_in[7];
    const float* tb1 = (const float*)d_in[8];
    const float* tW2 = (const float*)d_in[9];
    const float* tb2 = (const float*)d_in[10];
    const float* h0  = (const float*)d_in[11];
    const float* gh0 = (const float*)d_in[12];
    const float* f_Wh = (const float*)d_in[13];
    const float* f_bh = (const float*)d_in[14];
    const float* f_Wz = (const float*)d_in[15];
    const float* f_bz = (const float*)d_in[16];
    const float* g_Wh = (const float*)d_in[17];
    const float* g_bh = (const float*)d_in[18];
    const float* g_Wz = (const float*)d_in[19];
    const float* g_bz = (const float*)d_in[20];
    const float* d_W  = (const float*)d_in[21];
    const float* d_b  = (const float*)d_in[22];
    float* out = (float*)d_out;

    precompute_kernel<<<1, 512>>>(x_params, t_params, xW1, xb1, xW2, xb2,
                                  tW1, tb1, tW2, tb2, h0, gh0,
                                  f_Wh, f_bh, f_Wz, f_bz,
                                  g_Wh, g_bh, g_Wz, g_bz);

    cudaFuncSetAttribute(main_kernel, cudaFuncAttributeMaxDynamicSharedMemorySize,
                         SMEM_BYTES);
    main_kernel<<<NB * NN, 256, SMEM_BYTES>>>(coords, f_Wh, f_Wz, g_Wh, g_Wz,
                                              d_W, d_b, out);
}

// round 2
// speedup vs baseline: 1.5935x; 1.5935x over previous
#include <cuda_runtime.h>
#include <cstdint>

#define DIMK 32
#define NBLK 6
#define NB   16
#define NN   256

typedef unsigned long long ull;

// ---------------- precomputed per-(block,batch) fused biases ----------------
__device__ float d_fbias[NBLK * NB * DIMK];
__device__ float d_gbias[NBLK * NB * DIMK];

// ---------------- f32x2 helpers (Blackwell packed fp32) ----------------
__device__ __forceinline__ ull fma2(ull a, ull b, ull c) {
    ull d;
    asm("fma.rn.f32x2 %0, %1, %2, %3;" : "=l"(d) : "l"(a), "l"(b), "l"(c));
    return d;
}
__device__ __forceinline__ ull pack2(float lo, float hi) {
    ull r;
    asm("mov.b64 %0, {%1, %2};" : "=l"(r) : "f"(lo), "f"(hi));
    return r;
}
__device__ __forceinline__ void unpack2(ull v, float& lo, float& hi) {
    asm("mov.b64 {%0, %1}, %2;" : "=f"(lo), "=f"(hi) : "l"(v));
}

// ---------------- precompute kernel: ex/et MLPs + fused biases ----------------
__global__ void precompute_kernel(
    const float* __restrict__ x_params, const float* __restrict__ t_params,
    const float* __restrict__ xW1, const float* __restrict__ xb1,
    const float* __restrict__ xW2, const float* __restrict__ xb2,
    const float* __restrict__ tW1, const float* __restrict__ tb1,
    const float* __restrict__ tW2, const float* __restrict__ tb2,
    const float* __restrict__ h0,  const float* __restrict__ gh0,
    const float* __restrict__ f_Wh, const float* __restrict__ f_bh,
    const float* __restrict__ f_Wz, const float* __restrict__ f_bz,
    const float* __restrict__ g_Wh, const float* __restrict__ g_bh,
    const float* __restrict__ g_Wz, const float* __restrict__ g_bz)
{
    __shared__ float s1x[NB][DIMK], s1t[NB][DIMK], ex[NB][DIMK], et[NB][DIMK];
    int t = threadIdx.x;  // 512 threads == NB*DIMK
    {
        int b = t / DIMK, k = t % DIMK;
        float a = xb1[k];
        for (int p = 0; p < 16; p++) a += x_params[b * 16 + p] * xW1[p * DIMK + k];
        s1x[b][k] = sinf(a);
        float c = tb1[k];
        for (int p = 0; p < 8; p++) c += t_params[b * 8 + p] * tW1[p * DIMK + k];
        s1t[b][k] = sinf(c);
    }
    __syncthreads();
    {
        int b = t / DIMK, k = t % DIMK;
        float a = xb2[k], c = tb2[k];
        for (int m = 0; m < DIMK; m++) {
            a += s1x[b][m] * xW2[m * DIMK + k];
            c += s1t[b][m] * tW2[m * DIMK + k];
        }
        ex[b][k] = a;
        et[b][k] = c;
    }
    __syncthreads();
    for (int idx = t; idx < NBLK * NB * DIMK; idx += blockDim.x) {
        int blk = idx / (NB * DIMK);
        int b   = (idx / DIMK) % NB;
        int k   = idx % DIMK;
        float fa = f_bh[blk * DIMK + k] + f_bz[blk * DIMK + k];
        for (int m = 0; m < DIMK; m++)
            fa += et[b][m] * f_Wz[(blk * 34 + 2 + m) * DIMK + k];
        if (blk == 0)
            for (int m = 0; m < DIMK; m++)
                fa += h0[m] * f_Wh[m * DIMK + k];
        d_fbias[idx] = fa;
        float ga = g_bh[blk * DIMK + k] + g_bz[blk * DIMK + k];
        for (int m = 0; m < DIMK; m++)
            ga += ex[b][m] * g_Wz[(blk * 64 + 32 + m) * DIMK + k];
        if (blk == 0)
            for (int m = 0; m < DIMK; m++)
                ga += gh0[m] * g_Wh[m * DIMK + k];
        d_gbias[idx] = ga;
    }
}

// ---------------- smem layout (float offsets) — weights/biases only ----------------
#define OFF_FW  0        // f_Wh  [blk][m][k]   6*32*32 = 6144
#define OFF_GW  6144     // [g_Wh ; g_Wz[:32]]  [blk][m0..63][k] = 12288
#define OFF_WZ0 18432    // f_Wz row0  [blk][k] 192
#define OFF_WZ1 18624    // f_Wz row1  192
#define OFF_FB  18816    // fbias[blk][k], this batch, 192
#define OFF_GB  19008    // gbias, 192
#define OFF_DW  19200    // d_W, 32
#define SMEM_FLOATS 19232
#define SMEM_BYTES  (SMEM_FLOATS * 4)

__global__ void __launch_bounds__(256, 1) main_kernel(
    const float* __restrict__ coords,  // (B,N,2)
    const float* __restrict__ f_Wh,    // (6,32,32)
    const float* __restrict__ f_Wz,    // (6,34,32)
    const float* __restrict__ g_Wh,    // (6,32,32)
    const float* __restrict__ g_Wz,    // (6,64,32)
    const float* __restrict__ d_W,     // (32,1)
    const float* __restrict__ d_b,     // (1)
    float* __restrict__ out)           // (B,N,N)
{
    extern __shared__ float sm[];
    const int tid = threadIdx.x;
    const int b  = blockIdx.x >> 7;
    const int ip = blockIdx.x & 127;   // row pair: rows 2*ip, 2*ip+1

    // ---- cooperative smem staging ----
    for (int idx = tid; idx < 6144; idx += 256) sm[OFF_FW + idx] = f_Wh[idx];
    for (int idx = tid; idx < 12288; idx += 256) {
        int blk = idx >> 11;
        int rem = idx & 2047;
        int m = rem >> 5;
        int k = rem & 31;
        sm[OFF_GW + idx] = (m < 32) ? g_Wh[(blk << 10) + (m << 5) + k]
                                    : g_Wz[(blk << 11) + ((m - 32) << 5) + k];
    }
    for (int idx = tid; idx < NBLK * DIMK; idx += 256) {
        int blk = idx >> 5;
        int k = idx & 31;
        sm[OFF_WZ0 + idx] = f_Wz[(blk * 34 + 0) * DIMK + k];
        sm[OFF_WZ1 + idx] = f_Wz[(blk * 34 + 1) * DIMK + k];
        sm[OFF_FB + idx] = d_fbias[(blk * NB + b) * DIMK + k];
        sm[OFF_GB + idx] = d_gbias[(blk * NB + b) * DIMK + k];
    }
    if (tid < 32) sm[OFF_DW + tid] = d_W[tid];
    __syncthreads();

    const float x  = coords[(b * NN + tid) * 2 + 0];         // x_j, j = tid
    const float t0 = coords[(b * NN + 2 * ip) * 2 + 1];      // t row 2ip
    const float t1 = coords[(b * NN + 2 * ip + 1) * 2 + 1];  // t row 2ip+1

    // All state in registers:
    // h2[m]  = {h_m^e0, h_m^e1}
    // accA[p] = {a_{2p}^e0, a_{2p+1}^e0},  accB: elem1
    ull h2[32];
    ull accA[16], accB[16];

    // ================= f chain =================
#pragma unroll 1
    for (int blk = 0; blk < NBLK; blk++) {
        const float2* fb = (const float2*)(sm + OFF_FB + blk * 32);
        const float2* z0 = (const float2*)(sm + OFF_WZ0 + blk * 32);
        const float2* z1 = (const float2*)(sm + OFF_WZ1 + blk * 32);
#pragma unroll
        for (int p = 0; p < 16; p++) {
            float2 fbv = fb[p], z0v = z0[p], z1v = z1[p];
            float s0 = fmaf(x, z0v.x, fbv.x);
            float s1 = fmaf(x, z0v.y, fbv.y);
            accA[p] = pack2(fmaf(t0, z1v.x, s0), fmaf(t0, z1v.y, s1));
            accB[p] = pack2(fmaf(t1, z1v.x, s0), fmaf(t1, z1v.y, s1));
        }
        if (blk > 0) {
            const float* W = sm + OFF_FW + blk * 1024;
#pragma unroll
            for (int m = 0; m < 32; m++) {
                float he0, he1;
                unpack2(h2[m], he0, he1);
                ull a0 = pack2(he0, he0);
                ull a1 = pack2(he1, he1);
                const ulonglong2* wr = (const ulonglong2*)(W + m * 32);
#pragma unroll
                for (int q = 0; q < 8; q++) {
                    ulonglong2 w = wr[q];
                    accA[2 * q]     = fma2(a0, w.x, accA[2 * q]);
                    accA[2 * q + 1] = fma2(a0, w.y, accA[2 * q + 1]);
                    accB[2 * q]     = fma2(a1, w.x, accB[2 * q]);
                    accB[2 * q + 1] = fma2(a1, w.y, accB[2 * q + 1]);
                }
            }
        }
#pragma unroll
        for (int p = 0; p < 16; p++) {
            float aA0, aA1, aB0, aB1;
            unpack2(accA[p], aA0, aA1);
            unpack2(accB[p], aB0, aB1);
            h2[2 * p]     = pack2(__sinf(aA0), __sinf(aB0));
            h2[2 * p + 1] = pack2(__sinf(aA1), __sinf(aB1));
        }
    }

    // ================= g chain =================
    ull gh2[32];
#pragma unroll 1
    for (int blk = 0; blk < NBLK; blk++) {
        const float2* gb = (const float2*)(sm + OFF_GB + blk * 32);
#pragma unroll
        for (int p = 0; p < 16; p++) {
            float2 g2 = gb[p];
            ull v = pack2(g2.x, g2.y);
            accA[p] = v;
            accB[p] = v;
        }
        const float* W = sm + OFF_GW + blk * 2048;
        if (blk > 0) {
#pragma unroll
            for (int m = 0; m < 32; m++) {
                float ge0, ge1;
                unpack2(gh2[m], ge0, ge1);
                ull a0 = pack2(ge0, ge0);
                ull a1 = pack2(ge1, ge1);
                const ulonglong2* wr = (const ulonglong2*)(W + m * 32);
#pragma unroll
                for (int q = 0; q < 8; q++) {
                    ulonglong2 w = wr[q];
                    accA[2 * q]     = fma2(a0, w.x, accA[2 * q]);
                    accA[2 * q + 1] = fma2(a0, w.y, accA[2 * q + 1]);
                    accB[2 * q]     = fma2(a1, w.x, accB[2 * q]);
                    accB[2 * q + 1] = fma2(a1, w.y, accB[2 * q + 1]);
                }
            }
        }
        const float* Wz = W + 1024;  // h-part rows of g_Wz
#pragma unroll
        for (int m = 0; m < 32; m++) {
            float he0, he1;
            unpack2(h2[m], he0, he1);
            ull a0 = pack2(he0, he0);
            ull a1 = pack2(he1, he1);
            const ulonglong2* wr = (const ulonglong2*)(Wz + m * 32);
#pragma unroll
            for (int q = 0; q < 8; q++) {
                ulonglong2 w = wr[q];
                accA[2 * q]     = fma2(a0, w.x, accA[2 * q]);
                accA[2 * q + 1] = fma2(a0, w.y, accA[2 * q + 1]);
                accB[2 * q]     = fma2(a1, w.x, accB[2 * q]);
                accB[2 * q + 1] = fma2(a1, w.y, accB[2 * q + 1]);
            }
        }
#pragma unroll
        for (int p = 0; p < 16; p++) {
            float aA0, aA1, aB0, aB1;
            unpack2(accA[p], aA0, aA1);
            unpack2(accB[p], aB0, aB1);
            gh2[2 * p]     = pack2(__sinf(aA0), __sinf(aB0));
            gh2[2 * p + 1] = pack2(__sinf(aA1), __sinf(aB1));
        }
    }

    // ================= decode =================
    float u0 = d_b[0], u1 = u0;
    const float* dW = sm + OFF_DW;
#pragma unroll
    for (int m = 0; m < 32; m++) {
        float g0, g1;
        unpack2(gh2[m], g0, g1);
        float w = dW[m];
        u0 = fmaf(g0, w, u0);
        u1 = fmaf(g1, w, u1);
    }
    out[b * (NN * NN) + (2 * ip) * NN + tid]     = u0;
    out[b * (NN * NN) + (2 * ip + 1) * NN + tid] = u1;
}

// ---------------- launch ----------------
extern "C" void kernel_launch(void* const* d_in, const int* in_sizes, int n_in,
                              void* d_out, int out_size) {
    const float* coords   = (const float*)d_in[0];
    const float* x_params = (const float*)d_in[1];
    const float* t_params = (const float*)d_in[2];
    const float* xW1 = (const float*)d_in[3];
    const float* xb1 = (const float*)d_in[4];
    const float* xW2 = (const float*)d_in[5];
    const float* xb2 = (const float*)d_in[6];
    const float* tW1 = (const float*)d_in[7];
    const float* tb1 = (const float*)d_in[8];
    const float* tW2 = (const float*)d_in[9];
    const float* tb2 = (const float*)d_in[10];
    const float* h0  = (const float*)d_in[11];
    const float* gh0 = (const float*)d_in[12];
    const float* f_Wh = (const float*)d_in[13];
    const float* f_bh = (const float*)d_in[14];
    const float* f_Wz = (const float*)d_in[15];
    const float* f_bz = (const float*)d_in[16];
    const float* g_Wh = (const float*)d_in[17];
    const float* g_bh = (const float*)d_in[18];
    const float* g_Wz = (const float*)d_in[19];
    const float* g_bz = (const float*)d_in[20];
    const float* d_W  = (const float*)d_in[21];
    const float* d_b  = (const float*)d_in[22];
    float* out = (float*)d_out;

    precompute_kernel<<<1, 512>>>(x_params, t_params, xW1, xb1, xW2, xb2,
                                  tW1, tb1, tW2, tb2, h0, gh0,
                                  f_Wh, f_bh, f_Wz, f_bz,
                                  g_Wh, g_bh, g_Wz, g_bz);

    cudaFuncSetAttribute(main_kernel, cudaFuncAttributeMaxDynamicSharedMemorySize,
                         SMEM_BYTES);
    main_kernel<<<NB * (NN / 2), 256, SMEM_BYTES>>>(coords, f_Wh, f_Wz, g_Wh, g_Wz,
                                                    d_W, d_b, out);
}

// round 4
// speedup vs baseline: 3.3328x; 2.0915x over previous
#include <cuda_runtime.h>
#include <cuda_bf16.h>
#include <cstdint>

#define DIMK 32
#define NBLK 6
#define NB   16
#define NN   256
#define NITER 4

// ---------------- global scratch ----------------
__device__ float    d_fbias[NBLK * NB * DIMK];
__device__ float    d_gbias[NBLK * NB * DIMK];
// B fragments in exact mma.sync per-lane layout: [unit][lane][2 regs]
// units: 0..79   f blk1..5:  (blk-1)*16 + ver*8 + kt*4 + nt      (K=32)
//        80..95  g blk0:     80 + ver*8 + kt*4 + nt              (K=32, h part)
//        96..255 g blk1..5:  96 + (blk-1)*32 + ver*16 + kt*4+nt  (K=64)
__device__ uint32_t d_bfrag[256 * 64];

// ---------------- helpers ----------------
__device__ __forceinline__ uint32_t pack_bf16x2(float lo, float hi) {
    uint32_t r;
    asm("cvt.rn.bf16x2.f32 %0, %1, %2;" : "=r"(r) : "f"(hi), "f"(lo));
    return r;
}
__device__ __forceinline__ float2 unpack_bf16x2(uint32_t u) {
    float2 f;
    f.x = __uint_as_float(u << 16);
    f.y = __uint_as_float(u & 0xffff0000u);
    return f;
}
#define MMA16816(d, a, b) \
    asm volatile("mma.sync.aligned.m16n8k16.row.col.f32.bf16.bf16.f32 " \
        "{%0,%1,%2,%3}, {%4,%5,%6,%7}, {%8,%9}, {%0,%1,%2,%3};" \
        : "+f"((d)[0]), "+f"((d)[1]), "+f"((d)[2]), "+f"((d)[3]) \
        : "r"((a)[0]), "r"((a)[1]), "r"((a)[2]), "r"((a)[3]), \
          "r"((b)[0]), "r"((b)[1]))

// ---------------- precompute kernel ----------------
__global__ void precompute_kernel(
    const float* __restrict__ x_params, const float* __restrict__ t_params,
    const float* __restrict__ xW1, const float* __restrict__ xb1,
    const float* __restrict__ xW2, const float* __restrict__ xb2,
    const float* __restrict__ tW1, const float* __restrict__ tb1,
    const float* __restrict__ tW2, const float* __restrict__ tb2,
    const float* __restrict__ h0,  const float* __restrict__ gh0,
    const float* __restrict__ f_Wh, const float* __restrict__ f_bh,
    const float* __restrict__ f_Wz, const float* __restrict__ f_bz,
    const float* __restrict__ g_Wh, const float* __restrict__ g_bh,
    const float* __restrict__ g_Wz, const float* __restrict__ g_bz)
{
    __shared__ float s1x[NB][DIMK], s1t[NB][DIMK], ex[NB][DIMK], et[NB][DIMK];
    int t = threadIdx.x;  // 512 threads
    {
        int b = t / DIMK, k = t % DIMK;
        float a = xb1[k];
        for (int p = 0; p < 16; p++) a += x_params[b * 16 + p] * xW1[p * DIMK + k];
        s1x[b][k] = sinf(a);
        float c = tb1[k];
        for (int p = 0; p < 8; p++) c += t_params[b * 8 + p] * tW1[p * DIMK + k];
        s1t[b][k] = sinf(c);
    }
    __syncthreads();
    {
        int b = t / DIMK, k = t % DIMK;
        float a = xb2[k], c = tb2[k];
        for (int m = 0; m < DIMK; m++) {
            a += s1x[b][m] * xW2[m * DIMK + k];
            c += s1t[b][m] * tW2[m * DIMK + k];
        }
        ex[b][k] = a;
        et[b][k] = c;
    }
    __syncthreads();
    for (int idx = t; idx < NBLK * NB * DIMK; idx += blockDim.x) {
        int blk = idx / (NB * DIMK);
        int b   = (idx / DIMK) % NB;
        int k   = idx % DIMK;
        float fa = f_bh[blk * DIMK + k] + f_bz[blk * DIMK + k];
        for (int m = 0; m < DIMK; m++)
            fa += et[b][m] * f_Wz[(blk * 34 + 2 + m) * DIMK + k];
        if (blk == 0)
            for (int m = 0; m < DIMK; m++)
                fa += h0[m] * f_Wh[m * DIMK + k];
        d_fbias[idx] = fa;
        float ga = g_bh[blk * DIMK + k] + g_bz[blk * DIMK + k];
        for (int m = 0; m < DIMK; m++)
            ga += ex[b][m] * g_Wz[(blk * 64 + 32 + m) * DIMK + k];
        if (blk == 0)
            for (int m = 0; m < DIMK; m++)
                ga += gh0[m] * g_Wh[m * DIMK + k];
        d_gbias[idx] = ga;
    }
    // ---- B fragments (hi/lo split, per-lane mma layout) ----
    for (int e = t; e < 256 * 64; e += blockDim.x) {
        int u = e >> 6, r6 = e & 63, lane = r6 >> 1, reg = r6 & 1;
        int ver, kt, nt, blk, isG;
        if (u < 80)      { blk = u / 16 + 1; int q = u % 16; ver = q >> 3; kt = (q >> 2) & 1; nt = q & 3; isG = 0; }
        else if (u < 96) { int q = u - 80;   blk = 0;        ver = q >> 3; kt = (q >> 2) & 1; nt = q & 3; isG = 1; }
        else             { int q = u - 96;   blk = q / 32 + 1; q %= 32;    ver = q >> 4; kt = (q >> 2) & 3; nt = q & 3; isG = 1; }
        int k0 = kt * 16 + (lane & 3) * 2 + reg * 8;  // rows k0, k0+1
        int n  = nt * 8 + (lane >> 2);
        float w0, w1;
        if (!isG) {
            w0 = f_Wh[blk * 1024 + k0 * 32 + n];
            w1 = f_Wh[blk * 1024 + (k0 + 1) * 32 + n];
        } else if (blk == 0) {
            w0 = g_Wz[k0 * 32 + n];          // g blk0: h part rows 0..31
            w1 = g_Wz[(k0 + 1) * 32 + n];
        } else {
            w0 = (k0 < 32)     ? g_Wh[blk * 1024 + k0 * 32 + n]
                               : g_Wz[blk * 2048 + (k0 - 32) * 32 + n];
            int k1 = k0 + 1;
            w1 = (k1 < 32)     ? g_Wh[blk * 1024 + k1 * 32 + n]
                               : g_Wz[blk * 2048 + (k1 - 32) * 32 + n];
        }
        float h0f = __bfloat162float(__float2bfloat16_rn(w0));
        float h1f = __bfloat162float(__float2bfloat16_rn(w1));
        float v0 = ver ? (w0 - h0f) : h0f;
        float v1 = ver ? (w1 - h1f) : h1f;
        d_bfrag[e] = pack_bf16x2(v0, v1);   // low half = smaller k
    }
}

// ---------------- smem layout ----------------
#define SM_BF_U32 (256 * 64)                      // 16384 u32 = 64 KB
#define SMEM_BYTES (65536 + (192 * 5 + 64) * 4)

// ---------------- main kernel ----------------
__global__ void __launch_bounds__(256, 1) main_kernel(
    const float* __restrict__ coords,  // (B,N,2)
    const float* __restrict__ f_Wz,    // (6,34,32)
    const float* __restrict__ d_W,     // (32)
    const float* __restrict__ d_b,     // (1)
    float* __restrict__ out)           // (B,N,N)
{
    extern __shared__ char smem[];
    uint32_t* s_bf  = (uint32_t*)smem;
    float*    s_fb  = (float*)(smem + 65536);
    float*    s_z0  = s_fb + 192;
    float*    s_z1  = s_z0 + 192;
    float*    s_gb  = s_z1 + 192;
    float*    s_fbt = s_gb + 192;
    float*    s_dW  = s_fbt + 192;   // 32

    const int tid = threadIdx.x;
    const int w   = tid >> 5;
    const int lane = tid & 31;
    const int t4  = lane >> 2;
    const int m4  = lane & 3;
    const int b   = blockIdx.x >> 6;
    const int i0  = (blockIdx.x & 63) * NITER;

    // ---- stage B fragments + per-batch vectors ----
    {
        const uint4* src = (const uint4*)d_bfrag;
        uint4* dst = (uint4*)s_bf;
        for (int idx = tid; idx < SM_BF_U32 / 4; idx += 256) dst[idx] = src[idx];
    }
    for (int idx = tid; idx < 192; idx += 256) {
        int blk = idx >> 5, k = idx & 31;
        s_fb[idx] = d_fbias[(blk * NB + b) * DIMK + k];
        s_gb[idx] = d_gbias[(blk * NB + b) * DIMK + k];
        s_z0[idx] = f_Wz[(blk * 34 + 0) * DIMK + k];
        s_z1[idx] = f_Wz[(blk * 34 + 1) * DIMK + k];
    }
    if (tid < 32) s_dW[tid] = d_W[tid];
    __syncthreads();

    const float dbv = d_b[0];

    // x for this warp's rows (j = column index of output grid, fixed across i)
    float xr[2][2];
#pragma unroll
    for (int tt = 0; tt < 2; tt++) {
        int j = (w * 2 + tt) * 16 + t4;
        xr[tt][0] = coords[(b * NN + j) * 2 + 0];
        xr[tt][1] = coords[(b * NN + j + 8) * 2 + 0];
    }

    uint32_t ahi[2][8], alo[2][8], hh[2][8], hl[2][8];
    uint32_t bh[16][2], bl[16][2];
    float acc[2][4][4];

#pragma unroll 1
    for (int ii = 0; ii < NITER; ii++) {
        const int i = i0 + ii;
        const float tc = coords[(b * NN + i) * 2 + 1];
        __syncthreads();
        for (int idx = tid; idx < 192; idx += 256)
            s_fbt[idx] = s_fb[idx] + tc * s_z1[idx];
        __syncthreads();

        // ========== f blk0: h = sin(fbt + x*z0) ==========
#pragma unroll
        for (int tt = 0; tt < 2; tt++)
#pragma unroll
            for (int nt = 0; nt < 4; nt++) {
                int c = nt * 8 + m4 * 2;
                float2 fb2 = *(float2*)(s_fbt + c);
                float2 z02 = *(float2*)(s_z0 + c);
                float s0 = __sinf(fb2.x + xr[tt][0] * z02.x);
                float s1 = __sinf(fb2.y + xr[tt][0] * z02.y);
                float s2 = __sinf(fb2.x + xr[tt][1] * z02.x);
                float s3 = __sinf(fb2.y + xr[tt][1] * z02.y);
                int kt = nt >> 1, sl = (nt & 1) * 2;
                uint32_t p01 = pack_bf16x2(s0, s1);
                uint32_t p23 = pack_bf16x2(s2, s3);
                ahi[tt][kt * 4 + sl]     = p01;
                ahi[tt][kt * 4 + sl + 1] = p23;
                float2 r01 = unpack_bf16x2(p01), r23 = unpack_bf16x2(p23);
                alo[tt][kt * 4 + sl]     = pack_bf16x2(s0 - r01.x, s1 - r01.y);
                alo[tt][kt * 4 + sl + 1] = pack_bf16x2(s2 - r23.x, s3 - r23.y);
            }

        // ========== f blks 1..5 ==========
#pragma unroll 1
        for (int blk = 1; blk < NBLK; blk++) {
            const int ub = (blk - 1) * 16;
#pragma unroll
            for (int tt = 0; tt < 2; tt++)
#pragma unroll
                for (int nt = 0; nt < 4; nt++)
#pragma unroll
                    for (int q = 0; q < 4; q++) acc[tt][nt][q] = 0.0f;
#pragma unroll
            for (int q = 0; q < 8; q++) {
                uint2 v = *(const uint2*)(s_bf + (ub + q) * 64 + lane * 2);
                bh[q][0] = v.x; bh[q][1] = v.y;
            }
#pragma unroll
            for (int kt = 0; kt < 2; kt++)
#pragma unroll
                for (int nt = 0; nt < 4; nt++)
#pragma unroll
                    for (int tt = 0; tt < 2; tt++)
                        MMA16816(acc[tt][nt], &ahi[tt][kt * 4], bh[kt * 4 + nt]);
#pragma unroll
            for (int kt = 0; kt < 2; kt++)
#pragma unroll
                for (int nt = 0; nt < 4; nt++)
#pragma unroll
                    for (int tt = 0; tt < 2; tt++)
                        MMA16816(acc[tt][nt], &alo[tt][kt * 4], bh[kt * 4 + nt]);
#pragma unroll
            for (int q = 0; q < 8; q++) {
                uint2 v = *(const uint2*)(s_bf + (ub + 8 + q) * 64 + lane * 2);
                bl[q][0] = v.x; bl[q][1] = v.y;
            }
#pragma unroll
            for (int kt = 0; kt < 2; kt++)
#pragma unroll
                for (int nt = 0; nt < 4; nt++)
#pragma unroll
                    for (int tt = 0; tt < 2; tt++)
                        MMA16816(acc[tt][nt], &ahi[tt][kt * 4], bl[kt * 4 + nt]);
            // epilogue + rebuild
#pragma unroll
            for (int tt = 0; tt < 2; tt++)
#pragma unroll
                for (int nt = 0; nt < 4; nt++) {
                    int c = nt * 8 + m4 * 2;
                    float2 fb2 = *(float2*)(s_fbt + blk * 32 + c);
                    float2 z02 = *(float2*)(s_z0 + blk * 32 + c);
                    float s0 = __sinf(acc[tt][nt][0] + fb2.x + xr[tt][0] * z02.x);
                    float s1 = __sinf(acc[tt][nt][1] + fb2.y + xr[tt][0] * z02.y);
                    float s2 = __sinf(acc[tt][nt][2] + fb2.x + xr[tt][1] * z02.x);
                    float s3 = __sinf(acc[tt][nt][3] + fb2.y + xr[tt][1] * z02.y);
                    int kt = nt >> 1, sl = (nt & 1) * 2;
                    uint32_t p01 = pack_bf16x2(s0, s1);
                    uint32_t p23 = pack_bf16x2(s2, s3);
                    ahi[tt][kt * 4 + sl]     = p01;
                    ahi[tt][kt * 4 + sl + 1] = p23;
                    float2 r01 = unpack_bf16x2(p01), r23 = unpack_bf16x2(p23);
                    alo[tt][kt * 4 + sl]     = pack_bf16x2(s0 - r01.x, s1 - r01.y);
                    alo[tt][kt * 4 + sl + 1] = pack_bf16x2(s2 - r23.x, s3 - r23.y);
                }
        }

        // keep h fragments for the g chain
#pragma unroll
        for (int tt = 0; tt < 2; tt++)
#pragma unroll
            for (int q = 0; q < 8; q++) { hh[tt][q] = ahi[tt][q]; hl[tt][q] = alo[tt][q]; }

        // ========== g blk0 (K=32, A = h) ==========
        {
            const int ub = 80;
#pragma unroll
            for (int tt = 0; tt < 2; tt++)
#pragma unroll
                for (int nt = 0; nt < 4; nt++)
#pragma unroll
                    for (int q = 0; q < 4; q++) acc[tt][nt][q] = 0.0f;
#pragma unroll
            for (int q = 0; q < 8; q++) {
                uint2 v = *(const uint2*)(s_bf + (ub + q) * 64 + lane * 2);
                bh[q][0] = v.x; bh[q][1] = v.y;
            }
#pragma unroll
            for (int kt = 0; kt < 2; kt++)
#pragma unroll
                for (int nt = 0; nt < 4; nt++)
#pragma unroll
                    for (int tt = 0; tt < 2; tt++)
                        MMA16816(acc[tt][nt], &hh[tt][kt * 4], bh[kt * 4 + nt]);
#pragma unroll
            for (int kt = 0; kt < 2; kt++)
#pragma unroll
                for (int nt = 0; nt < 4; nt++)
#pragma unroll
                    for (int tt = 0; tt < 2; tt++)
                        MMA16816(acc[tt][nt], &hl[tt][kt * 4], bh[kt * 4 + nt]);
#pragma unroll
            for (int q = 0; q < 8; q++) {
                uint2 v = *(const uint2*)(s_bf + (ub + 8 + q) * 64 + lane * 2);
                bl[q][0] = v.x; bl[q][1] = v.y;
            }
#pragma unroll
            for (int kt = 0; kt < 2; kt++)
#pragma unroll
                for (int nt = 0; nt < 4; nt++)
#pragma unroll
                    for (int tt = 0; tt < 2; tt++)
                        MMA16816(acc[tt][nt], &hh[tt][kt * 4], bl[kt * 4 + nt]);
#pragma unroll
            for (int tt = 0; tt < 2; tt++)
#pragma unroll
                for (int nt = 0; nt < 4; nt++) {
                    int c = nt * 8 + m4 * 2;
                    float2 gb2 = *(float2*)(s_gb + c);
                    float s0 = __sinf(acc[tt][nt][0] + gb2.x);
                    float s1 = __sinf(acc[tt][nt][1] + gb2.y);
                    float s2 = __sinf(acc[tt][nt][2] + gb2.x);
                    float s3 = __sinf(acc[tt][nt][3] + gb2.y);
                    int kt = nt >> 1, sl = (nt & 1) * 2;
                    uint32_t p01 = pack_bf16x2(s0, s1);
                    uint32_t p23 = pack_bf16x2(s2, s3);
                    ahi[tt][kt * 4 + sl]     = p01;
                    ahi[tt][kt * 4 + sl + 1] = p23;
                    float2 r01 = unpack_bf16x2(p01), r23 = unpack_bf16x2(p23);
                    alo[tt][kt * 4 + sl]     = pack_bf16x2(s0 - r01.x, s1 - r01.y);
                    alo[tt][kt * 4 + sl + 1] = pack_bf16x2(s2 - r23.x, s3 - r23.y);
                }
        }

        // ========== g blks 1..5 (K=64: A = [gh ; h]) ==========
        float p0[2], p1[2];
#pragma unroll
        for (int tt = 0; tt < 2; tt++) { p0[tt] = 0.0f; p1[tt] = 0.0f; }

#pragma unroll 1
        for (int blk = 1; blk < NBLK; blk++) {
            const int ub = 96 + (blk - 1) * 32;
#pragma unroll
            for (int tt = 0; tt < 2; tt++)
#pragma unroll
                for (int nt = 0; nt < 4; nt++)
#pragma unroll
                    for (int q = 0; q < 4; q++) acc[tt][nt][q] = 0.0f;
#pragma unroll
            for (int q = 0; q < 16; q++) {
                uint2 v = *(const uint2*)(s_bf + (ub + q) * 64 + lane * 2);
                bh[q][0] = v.x; bh[q][1] = v.y;
            }
            // pass 1: hi
#pragma unroll
            for (int kt = 0; kt < 2; kt++)
#pragma unroll
                for (int nt = 0; nt < 4; nt++)
#pragma unroll
                    for (int tt = 0; tt < 2; tt++)
                        MMA16816(acc[tt][nt], &ahi[tt][kt * 4], bh[kt * 4 + nt]);
#pragma unroll
            for (int kt = 0; kt < 2; kt++)
#pragma unroll
                for (int nt = 0; nt < 4; nt++)
#pragma unroll
                    for (int tt = 0; tt < 2; tt++)
                        MMA16816(acc[tt][nt], &hh[tt][kt * 4], bh[(kt + 2) * 4 + nt]);
            // pass 2: lo·Bhi
#pragma unroll
            for (int kt = 0; kt < 2; kt++)
#pragma unroll
                for (int nt = 0; nt < 4; nt++)
#pragma unroll
                    for (int tt = 0; tt < 2; tt++)
                        MMA16816(acc[tt][nt], &alo[tt][kt * 4], bh[kt * 4 + nt]);
#pragma unroll
            for (int kt = 0; kt < 2; kt++)
#pragma unroll
                for (int nt = 0; nt < 4; nt++)
#pragma unroll
                    for (int tt = 0; tt < 2; tt++)
                        MMA16816(acc[tt][nt], &hl[tt][kt * 4], bh[(kt + 2) * 4 + nt]);
            // pass 3: hi·Blo
#pragma unroll
            for (int q = 0; q < 16; q++) {
                uint2 v = *(const uint2*)(s_bf + (ub + 16 + q) * 64 + lane * 2);
                bl[q][0] = v.x; bl[q][1] = v.y;
            }
#pragma unroll
            for (int kt = 0; kt < 2; kt++)
#pragma unroll
                for (int nt = 0; nt < 4; nt++)
#pragma unroll
                    for (int tt = 0; tt < 2; tt++)
                        MMA16816(acc[tt][nt], &ahi[tt][kt * 4], bl[kt * 4 + nt]);
#pragma unroll
            for (int kt = 0; kt < 2; kt++)
#pragma unroll
                for (int nt = 0; nt < 4; nt++)
#pragma unroll
                    for (int tt = 0; tt < 2; tt++)
                        MMA16816(acc[tt][nt], &hh[tt][kt * 4], bl[(kt + 2) * 4 + nt]);

            const bool last = (blk == NBLK - 1);
#pragma unroll
            for (int tt = 0; tt < 2; tt++)
#pragma unroll
                for (int nt = 0; nt < 4; nt++) {
                    int c = nt * 8 + m4 * 2;
                    float2 gb2 = *(float2*)(s_gb + blk * 32 + c);
                    float s0 = __sinf(acc[tt][nt][0] + gb2.x);
                    float s1 = __sinf(acc[tt][nt][1] + gb2.y);
                    float s2 = __sinf(acc[tt][nt][2] + gb2.x);
                    float s3 = __sinf(acc[tt][nt][3] + gb2.y);
                    if (!last) {
                        int kt = nt >> 1, sl = (nt & 1) * 2;
                        uint32_t p01 = pack_bf16x2(s0, s1);
                        uint32_t p23 = pack_bf16x2(s2, s3);
                        ahi[tt][kt * 4 + sl]     = p01;
                        ahi[tt][kt * 4 + sl + 1] = p23;
                        float2 r01 = unpack_bf16x2(p01), r23 = unpack_bf16x2(p23);
                        alo[tt][kt * 4 + sl]     = pack_bf16x2(s0 - r01.x, s1 - r01.y);
                        alo[tt][kt * 4 + sl + 1] = pack_bf16x2(s2 - r23.x, s3 - r23.y);
                    } else {
                        float2 dw2 = *(float2*)(s_dW + c);
                        p0[tt] += s0 * dw2.x + s1 * dw2.y;
                        p1[tt] += s2 * dw2.x + s3 * dw2.y;
                    }
                }
        }

        // ========== decode reduce + store ==========
#pragma unroll
        for (int tt = 0; tt < 2; tt++) {
            p0[tt] += __shfl_xor_sync(0xffffffffu, p0[tt], 1);
            p0[tt] += __shfl_xor_sync(0xffffffffu, p0[tt], 2);
            p1[tt] += __shfl_xor_sync(0xffffffffu, p1[tt], 1);
            p1[tt] += __shfl_xor_sync(0xffffffffu, p1[tt], 2);
            if (m4 == 0) {
                int r0 = (w * 2 + tt) * 16 + t4;
                out[b * (NN * NN) + i * NN + r0]     = p0[tt] + dbv;
                out[b * (NN * NN) + i * NN + r0 + 8] = p1[tt] + dbv;
            }
        }
    }
}

// ---------------- launch ----------------
extern "C" void kernel_launch(void* const* d_in, const int* in_sizes, int n_in,
                              void* d_out, int out_size) {
    const float* coords   = (const float*)d_in[0];
    const float* x_params = (const float*)d_in[1];
    const float* t_params = (const float*)d_in[2];
    const float* xW1 = (const float*)d_in[3];
    const float* xb1 = (const float*)d_in[4];
    const float* xW2 = (const float*)d_in[5];
    const float* xb2 = (const float*)d_in[6];
    const float* tW1 = (const float*)d_in[7];
    const float* tb1 = (const float*)d_in[8];
    const float* tW2 = (const float*)d_in[9];
    const float* tb2 = (const float*)d_in[10];
    const float* h0  = (const float*)d_in[11];
    const float* gh0 = (const float*)d_in[12];
    const float* f_Wh = (const float*)d_in[13];
    const float* f_bh = (const float*)d_in[14];
    const float* f_Wz = (const float*)d_in[15];
    const float* f_bz = (const float*)d_in[16];
    const float* g_Wh = (const float*)d_in[17];
    const float* g_bh = (const float*)d_in[18];
    const float* g_Wz = (const float*)d_in[19];
    const float* g_bz = (const float*)d_in[20];
    const float* d_W  = (const float*)d_in[21];
    const float* d_b  = (const float*)d_in[22];
    float* out = (float*)d_out;

    precompute_kernel<<<1, 512>>>(x_params, t_params, xW1, xb1, xW2, xb2,
                                  tW1, tb1, tW2, tb2, h0, gh0,
                                  f_Wh, f_bh, f_Wz, f_bz,
                                  g_Wh, g_bh, g_Wz, g_bz);

    cudaFuncSetAttribute(main_kernel, cudaFuncAttributeMaxDynamicSharedMemorySize,
                         SMEM_BYTES);
    main_kernel<<<NB * (NN / NITER), 256, SMEM_BYTES>>>(coords, f_Wz, d_W, d_b, out);
}

// round 5
// speedup vs baseline: 3.6366x; 1.0912x over previous
#include <cuda_runtime.h>
#include <cuda_bf16.h>
#include <cstdint>

#define DIMK 32
#define NBLK 6
#define NB   16
#define NN   256
#define NITER 4

// ---------------- global scratch ----------------
__device__ float    d_fbias[NBLK * NB * DIMK];
__device__ float    d_gbias[NBLK * NB * DIMK];
// B fragments in exact mma.sync per-lane layout: [unit][lane][2 regs]
// units: 0..79   f blk1..5:  (blk-1)*16 + ver*8 + kt*4 + nt      (K=32)
//        80..95  g blk0:     80 + ver*8 + kt*4 + nt              (K=32, h part)
//        96..255 g blk1..5:  96 + (blk-1)*32 + ver*16 + kt*4+nt  (K=64)
__device__ uint32_t d_bfrag[256 * 64];

// ---------------- helpers ----------------
__device__ __forceinline__ uint32_t pack_bf16x2(float lo, float hi) {
    uint32_t r;
    asm("cvt.rn.bf16x2.f32 %0, %1, %2;" : "=r"(r) : "f"(hi), "f"(lo));
    return r;
}
__device__ __forceinline__ float2 unpack_bf16x2(uint32_t u) {
    float2 f;
    f.x = __uint_as_float(u << 16);
    f.y = __uint_as_float(u & 0xffff0000u);
    return f;
}
#define MMA16816(d, a, b) \
    asm volatile("mma.sync.aligned.m16n8k16.row.col.f32.bf16.bf16.f32 " \
        "{%0,%1,%2,%3}, {%4,%5,%6,%7}, {%8,%9}, {%0,%1,%2,%3};" \
        : "+f"((d)[0]), "+f"((d)[1]), "+f"((d)[2]), "+f"((d)[3]) \
        : "r"((a)[0]), "r"((a)[1]), "r"((a)[2]), "r"((a)[3]), \
          "r"((b)[0]), "r"((b)[1]))

// chunk: load 4 B units (8 regs) and run both A variants against them
#define CHUNK2(ubase, A0p, A1p, A0s, A1s) do {                                   \
    uint32_t Bc[4][2];                                                           \
    _Pragma("unroll")                                                            \
    for (int nt = 0; nt < 4; nt++) {                                             \
        uint2 v = *(const uint2*)(s_bf + ((ubase) + nt) * 64 + lane * 2);        \
        Bc[nt][0] = v.x; Bc[nt][1] = v.y;                                        \
    }                                                                            \
    _Pragma("unroll")                                                            \
    for (int nt = 0; nt < 4; nt++) {                                             \
        MMA16816(acc[0][nt], (A0p), Bc[nt]);                                     \
        MMA16816(acc[1][nt], (A1p), Bc[nt]);                                     \
    }                                                                            \
    _Pragma("unroll")                                                            \
    for (int nt = 0; nt < 4; nt++) {                                             \
        MMA16816(acc[0][nt], (A0s), Bc[nt]);                                     \
        MMA16816(acc[1][nt], (A1s), Bc[nt]);                                     \
    }                                                                            \
} while (0)

#define CHUNK1(ubase, A0p, A1p) do {                                             \
    uint32_t Bc[4][2];                                                           \
    _Pragma("unroll")                                                            \
    for (int nt = 0; nt < 4; nt++) {                                             \
        uint2 v = *(const uint2*)(s_bf + ((ubase) + nt) * 64 + lane * 2);        \
        Bc[nt][0] = v.x; Bc[nt][1] = v.y;                                        \
    }                                                                            \
    _Pragma("unroll")                                                            \
    for (int nt = 0; nt < 4; nt++) {                                             \
        MMA16816(acc[0][nt], (A0p), Bc[nt]);                                     \
        MMA16816(acc[1][nt], (A1p), Bc[nt]);                                     \
    }                                                                            \
} while (0)

// ---------------- precompute kernel ----------------
__global__ void precompute_kernel(
    const float* __restrict__ x_params, const float* __restrict__ t_params,
    const float* __restrict__ xW1, const float* __restrict__ xb1,
    const float* __restrict__ xW2, const float* __restrict__ xb2,
    const float* __restrict__ tW1, const float* __restrict__ tb1,
    const float* __restrict__ tW2, const float* __restrict__ tb2,
    const float* __restrict__ h0,  const float* __restrict__ gh0,
    const float* __restrict__ f_Wh, const float* __restrict__ f_bh,
    const float* __restrict__ f_Wz, const float* __restrict__ f_bz,
    const float* __restrict__ g_Wh, const float* __restrict__ g_bh,
    const float* __restrict__ g_Wz, const float* __restrict__ g_bz)
{
    __shared__ float s1x[NB][DIMK], s1t[NB][DIMK], ex[NB][DIMK], et[NB][DIMK];
    int t = threadIdx.x;  // 512 threads
    {
        int b = t / DIMK, k = t % DIMK;
        float a = xb1[k];
        for (int p = 0; p < 16; p++) a += x_params[b * 16 + p] * xW1[p * DIMK + k];
        s1x[b][k] = sinf(a);
        float c = tb1[k];
        for (int p = 0; p < 8; p++) c += t_params[b * 8 + p] * tW1[p * DIMK + k];
        s1t[b][k] = sinf(c);
    }
    __syncthreads();
    {
        int b = t / DIMK, k = t % DIMK;
        float a = xb2[k], c = tb2[k];
        for (int m = 0; m < DIMK; m++) {
            a += s1x[b][m] * xW2[m * DIMK + k];
            c += s1t[b][m] * tW2[m * DIMK + k];
        }
        ex[b][k] = a;
        et[b][k] = c;
    }
    __syncthreads();
    for (int idx = t; idx < NBLK * NB * DIMK; idx += blockDim.x) {
        int blk = idx / (NB * DIMK);
        int b   = (idx / DIMK) % NB;
        int k   = idx % DIMK;
        float fa = f_bh[blk * DIMK + k] + f_bz[blk * DIMK + k];
        for (int m = 0; m < DIMK; m++)
            fa += et[b][m] * f_Wz[(blk * 34 + 2 + m) * DIMK + k];
        if (blk == 0)
            for (int m = 0; m < DIMK; m++)
                fa += h0[m] * f_Wh[m * DIMK + k];
        d_fbias[idx] = fa;
        float ga = g_bh[blk * DIMK + k] + g_bz[blk * DIMK + k];
        for (int m = 0; m < DIMK; m++)
            ga += ex[b][m] * g_Wz[(blk * 64 + 32 + m) * DIMK + k];
        if (blk == 0)
            for (int m = 0; m < DIMK; m++)
                ga += gh0[m] * g_Wh[m * DIMK + k];
        d_gbias[idx] = ga;
    }
    // ---- B fragments (hi/lo split, per-lane mma layout) ----
    for (int e = t; e < 256 * 64; e += blockDim.x) {
        int u = e >> 6, r6 = e & 63, lane = r6 >> 1, reg = r6 & 1;
        int ver, kt, nt, blk, isG;
        if (u < 80)      { blk = u / 16 + 1; int q = u % 16; ver = q >> 3; kt = (q >> 2) & 1; nt = q & 3; isG = 0; }
        else if (u < 96) { int q = u - 80;   blk = 0;        ver = q >> 3; kt = (q >> 2) & 1; nt = q & 3; isG = 1; }
        else             { int q = u - 96;   blk = q / 32 + 1; q %= 32;    ver = q >> 4; kt = (q >> 2) & 3; nt = q & 3; isG = 1; }
        int k0 = kt * 16 + (lane & 3) * 2 + reg * 8;  // rows k0, k0+1
        int n  = nt * 8 + (lane >> 2);
        float w0, w1;
        if (!isG) {
            w0 = f_Wh[blk * 1024 + k0 * 32 + n];
            w1 = f_Wh[blk * 1024 + (k0 + 1) * 32 + n];
        } else if (blk == 0) {
            w0 = g_Wz[k0 * 32 + n];          // g blk0: h part rows 0..31
            w1 = g_Wz[(k0 + 1) * 32 + n];
        } else {
            w0 = (k0 < 32)     ? g_Wh[blk * 1024 + k0 * 32 + n]
                               : g_Wz[blk * 2048 + (k0 - 32) * 32 + n];
            int k1 = k0 + 1;
            w1 = (k1 < 32)     ? g_Wh[blk * 1024 + k1 * 32 + n]
                               : g_Wz[blk * 2048 + (k1 - 32) * 32 + n];
        }
        float h0f = __bfloat162float(__float2bfloat16_rn(w0));
        float h1f = __bfloat162float(__float2bfloat16_rn(w1));
        float v0 = ver ? (w0 - h0f) : h0f;
        float v1 = ver ? (w1 - h1f) : h1f;
        d_bfrag[e] = pack_bf16x2(v0, v1);   // low half = smaller k
    }
}

// ---------------- smem layout ----------------
#define SM_BF_U32 (256 * 64)                      // 16384 u32 = 64 KB
#define SMEM_BYTES (65536 + (192 * 5 + 64) * 4)

// ---------------- main kernel ----------------
__global__ void __launch_bounds__(256, 2) main_kernel(
    const float* __restrict__ coords,  // (B,N,2)
    const float* __restrict__ f_Wz,    // (6,34,32)
    const float* __restrict__ d_W,     // (32)
    const float* __restrict__ d_b,     // (1)
    float* __restrict__ out)           // (B,N,N)
{
    extern __shared__ char smem[];
    uint32_t* s_bf  = (uint32_t*)smem;
    float*    s_fb  = (float*)(smem + 65536);
    float*    s_z0  = s_fb + 192;
    float*    s_z1  = s_z0 + 192;
    float*    s_gb  = s_z1 + 192;
    float*    s_fbt = s_gb + 192;
    float*    s_dW  = s_fbt + 192;   // 32

    const int tid = threadIdx.x;
    const int w   = tid >> 5;
    const int lane = tid & 31;
    const int t4  = lane >> 2;
    const int m4  = lane & 3;
    const int b   = blockIdx.x >> 6;
    const int i0  = (blockIdx.x & 63) * NITER;

    // ---- stage B fragments + per-batch vectors ----
    {
        const uint4* src = (const uint4*)d_bfrag;
        uint4* dst = (uint4*)s_bf;
        for (int idx = tid; idx < SM_BF_U32 / 4; idx += 256) dst[idx] = src[idx];
    }
    for (int idx = tid; idx < 192; idx += 256) {
        int blk = idx >> 5, k = idx & 31;
        s_fb[idx] = d_fbias[(blk * NB + b) * DIMK + k];
        s_gb[idx] = d_gbias[(blk * NB + b) * DIMK + k];
        s_z0[idx] = f_Wz[(blk * 34 + 0) * DIMK + k];
        s_z1[idx] = f_Wz[(blk * 34 + 1) * DIMK + k];
    }
    if (tid < 32) s_dW[tid] = d_W[tid];
    __syncthreads();

    const float dbv = d_b[0];

    // x for this warp's rows (j = column index of output grid, fixed across i)
    float xr[2][2];
#pragma unroll
    for (int tt = 0; tt < 2; tt++) {
        int j = (w * 2 + tt) * 16 + t4;
        xr[tt][0] = coords[(b * NN + j) * 2 + 0];
        xr[tt][1] = coords[(b * NN + j + 8) * 2 + 0];
    }

    uint32_t ahi[2][8], alo[2][8], hh[2][8], hl[2][8];
    float acc[2][4][4];

#pragma unroll 1
    for (int ii = 0; ii < NITER; ii++) {
        const int i = i0 + ii;
        const float tc = coords[(b * NN + i) * 2 + 1];
        __syncthreads();
        for (int idx = tid; idx < 192; idx += 256)
            s_fbt[idx] = s_fb[idx] + tc * s_z1[idx];
        __syncthreads();

        // ========== f blk0: h = sin(fbt + x*z0) ==========
#pragma unroll
        for (int tt = 0; tt < 2; tt++)
#pragma unroll
            for (int nt = 0; nt < 4; nt++) {
                int c = nt * 8 + m4 * 2;
                float2 fb2 = *(float2*)(s_fbt + c);
                float2 z02 = *(float2*)(s_z0 + c);
                float s0 = __sinf(fb2.x + xr[tt][0] * z02.x);
                float s1 = __sinf(fb2.y + xr[tt][0] * z02.y);
                float s2 = __sinf(fb2.x + xr[tt][1] * z02.x);
                float s3 = __sinf(fb2.y + xr[tt][1] * z02.y);
                int kt = nt >> 1, sl = (nt & 1) * 2;
                uint32_t p01 = pack_bf16x2(s0, s1);
                uint32_t p23 = pack_bf16x2(s2, s3);
                ahi[tt][kt * 4 + sl]     = p01;
                ahi[tt][kt * 4 + sl + 1] = p23;
                float2 r01 = unpack_bf16x2(p01), r23 = unpack_bf16x2(p23);
                alo[tt][kt * 4 + sl]     = pack_bf16x2(s0 - r01.x, s1 - r01.y);
                alo[tt][kt * 4 + sl + 1] = pack_bf16x2(s2 - r23.x, s3 - r23.y);
            }

        // ========== f blks 1..5 (K=32, A = h-prev) ==========
#pragma unroll 1
        for (int blk = 1; blk < NBLK; blk++) {
            const int ub = (blk - 1) * 16;
#pragma unroll
            for (int tt = 0; tt < 2; tt++)
#pragma unroll
                for (int nt = 0; nt < 4; nt++)
#pragma unroll
                    for (int q = 0; q < 4; q++) acc[tt][nt][q] = 0.0f;
#pragma unroll
            for (int kt = 0; kt < 2; kt++) {
                CHUNK2(ub + kt * 4, &ahi[0][kt * 4], &ahi[1][kt * 4],
                       &alo[0][kt * 4], &alo[1][kt * 4]);
                CHUNK1(ub + 8 + kt * 4, &ahi[0][kt * 4], &ahi[1][kt * 4]);
            }
            // epilogue + rebuild
#pragma unroll
            for (int tt = 0; tt < 2; tt++)
#pragma unroll
                for (int nt = 0; nt < 4; nt++) {
                    int c = nt * 8 + m4 * 2;
                    float2 fb2 = *(float2*)(s_fbt + blk * 32 + c);
                    float2 z02 = *(float2*)(s_z0 + blk * 32 + c);
                    float s0 = __sinf(acc[tt][nt][0] + fb2.x + xr[tt][0] * z02.x);
                    float s1 = __sinf(acc[tt][nt][1] + fb2.y + xr[tt][0] * z02.y);
                    float s2 = __sinf(acc[tt][nt][2] + fb2.x + xr[tt][1] * z02.x);
                    float s3 = __sinf(acc[tt][nt][3] + fb2.y + xr[tt][1] * z02.y);
                    int kt = nt >> 1, sl = (nt & 1) * 2;
                    uint32_t p01 = pack_bf16x2(s0, s1);
                    uint32_t p23 = pack_bf16x2(s2, s3);
                    ahi[tt][kt * 4 + sl]     = p01;
                    ahi[tt][kt * 4 + sl + 1] = p23;
                    float2 r01 = unpack_bf16x2(p01), r23 = unpack_bf16x2(p23);
                    alo[tt][kt * 4 + sl]     = pack_bf16x2(s0 - r01.x, s1 - r01.y);
                    alo[tt][kt * 4 + sl + 1] = pack_bf16x2(s2 - r23.x, s3 - r23.y);
                }
        }

        // keep h fragments for the g chain
#pragma unroll
        for (int tt = 0; tt < 2; tt++)
#pragma unroll
            for (int q = 0; q < 8; q++) { hh[tt][q] = ahi[tt][q]; hl[tt][q] = alo[tt][q]; }

        // ========== g blk0 (K=32, A = h) ==========
        {
            const int ub = 80;
#pragma unroll
            for (int tt = 0; tt < 2; tt++)
#pragma unroll
                for (int nt = 0; nt < 4; nt++)
#pragma unroll
                    for (int q = 0; q < 4; q++) acc[tt][nt][q] = 0.0f;
#pragma unroll
            for (int kt = 0; kt < 2; kt++) {
                CHUNK2(ub + kt * 4, &hh[0][kt * 4], &hh[1][kt * 4],
                       &hl[0][kt * 4], &hl[1][kt * 4]);
                CHUNK1(ub + 8 + kt * 4, &hh[0][kt * 4], &hh[1][kt * 4]);
            }
#pragma unroll
            for (int tt = 0; tt < 2; tt++)
#pragma unroll
                for (int nt = 0; nt < 4; nt++) {
                    int c = nt * 8 + m4 * 2;
                    float2 gb2 = *(float2*)(s_gb + c);
                    float s0 = __sinf(acc[tt][nt][0] + gb2.x);
                    float s1 = __sinf(acc[tt][nt][1] + gb2.y);
                    float s2 = __sinf(acc[tt][nt][2] + gb2.x);
                    float s3 = __sinf(acc[tt][nt][3] + gb2.y);
                    int kt = nt >> 1, sl = (nt & 1) * 2;
                    uint32_t p01 = pack_bf16x2(s0, s1);
                    uint32_t p23 = pack_bf16x2(s2, s3);
                    ahi[tt][kt * 4 + sl]     = p01;
                    ahi[tt][kt * 4 + sl + 1] = p23;
                    float2 r01 = unpack_bf16x2(p01), r23 = unpack_bf16x2(p23);
                    alo[tt][kt * 4 + sl]     = pack_bf16x2(s0 - r01.x, s1 - r01.y);
                    alo[tt][kt * 4 + sl + 1] = pack_bf16x2(s2 - r23.x, s3 - r23.y);
                }
        }

        // ========== g blks 1..5 (K=64: A = [gh ; h]) ==========
        float p0[2], p1[2];
#pragma unroll
        for (int tt = 0; tt < 2; tt++) { p0[tt] = 0.0f; p1[tt] = 0.0f; }

#pragma unroll 1
        for (int blk = 1; blk < NBLK; blk++) {
            const int ub = 96 + (blk - 1) * 32;
#pragma unroll
            for (int tt = 0; tt < 2; tt++)
#pragma unroll
                for (int nt = 0; nt < 4; nt++)
#pragma unroll
                    for (int q = 0; q < 4; q++) acc[tt][nt][q] = 0.0f;
            // kt 0,1: gh part; kt 2,3: h part
#pragma unroll
            for (int kt = 0; kt < 2; kt++) {
                CHUNK2(ub + kt * 4, &ahi[0][kt * 4], &ahi[1][kt * 4],
                       &alo[0][kt * 4], &alo[1][kt * 4]);
                CHUNK1(ub + 16 + kt * 4, &ahi[0][kt * 4], &ahi[1][kt * 4]);
            }
#pragma unroll
            for (int kt = 0; kt < 2; kt++) {
                CHUNK2(ub + 8 + kt * 4, &hh[0][kt * 4], &hh[1][kt * 4],
                       &hl[0][kt * 4], &hl[1][kt * 4]);
                CHUNK1(ub + 24 + kt * 4, &hh[0][kt * 4], &hh[1][kt * 4]);
            }

            const bool last = (blk == NBLK - 1);
#pragma unroll
            for (int tt = 0; tt < 2; tt++)
#pragma unroll
                for (int nt = 0; nt < 4; nt++) {
                    int c = nt * 8 + m4 * 2;
                    float2 gb2 = *(float2*)(s_gb + blk * 32 + c);
                    float s0 = __sinf(acc[tt][nt][0] + gb2.x);
                    float s1 = __sinf(acc[tt][nt][1] + gb2.y);
                    float s2 = __sinf(acc[tt][nt][2] + gb2.x);
                    float s3 = __sinf(acc[tt][nt][3] + gb2.y);
                    if (!last) {
                        int kt = nt >> 1, sl = (nt & 1) * 2;
                        uint32_t p01 = pack_bf16x2(s0, s1);
                        uint32_t p23 = pack_bf16x2(s2, s3);
                        ahi[tt][kt * 4 + sl]     = p01;
                        ahi[tt][kt * 4 + sl + 1] = p23;
                        float2 r01 = unpack_bf16x2(p01), r23 = unpack_bf16x2(p23);
                        alo[tt][kt * 4 + sl]     = pack_bf16x2(s0 - r01.x, s1 - r01.y);
                        alo[tt][kt * 4 + sl + 1] = pack_bf16x2(s2 - r23.x, s3 - r23.y);
                    } else {
                        float2 dw2 = *(float2*)(s_dW + c);
                        p0[tt] += s0 * dw2.x + s1 * dw2.y;
                        p1[tt] += s2 * dw2.x + s3 * dw2.y;
                    }
                }
        }

        // ========== decode reduce + store ==========
#pragma unroll
        for (int tt = 0; tt < 2; tt++) {
            p0[tt] += __shfl_xor_sync(0xffffffffu, p0[tt], 1);
            p0[tt] += __shfl_xor_sync(0xffffffffu, p0[tt], 2);
            p1[tt] += __shfl_xor_sync(0xffffffffu, p1[tt], 1);
            p1[tt] += __shfl_xor_sync(0xffffffffu, p1[tt], 2);
            if (m4 == 0) {
                int r0 = (w * 2 + tt) * 16 + t4;
                out[b * (NN * NN) + i * NN + r0]     = p0[tt] + dbv;
                out[b * (NN * NN) + i * NN + r0 + 8] = p1[tt] + dbv;
            }
        }
    }
}

// ---------------- launch ----------------
extern "C" void kernel_launch(void* const* d_in, const int* in_sizes, int n_in,
                              void* d_out, int out_size) {
    const float* coords   = (const float*)d_in[0];
    const float* x_params = (const float*)d_in[1];
    const float* t_params = (const float*)d_in[2];
    const float* xW1 = (const float*)d_in[3];
    const float* xb1 = (const float*)d_in[4];
    const float* xW2 = (const float*)d_in[5];
    const float* xb2 = (const float*)d_in[6];
    const float* tW1 = (const float*)d_in[7];
    const float* tb1 = (const float*)d_in[8];
    const float* tW2 = (const float*)d_in[9];
    const float* tb2 = (const float*)d_in[10];
    const float* h0  = (const float*)d_in[11];
    const float* gh0 = (const float*)d_in[12];
    const float* f_Wh = (const float*)d_in[13];
    const float* f_bh = (const float*)d_in[14];
    const float* f_Wz = (const float*)d_in[15];
    const float* f_bz = (const float*)d_in[16];
    const float* g_Wh = (const float*)d_in[17];
    const float* g_bh = (const float*)d_in[18];
    const float* g_Wz = (const float*)d_in[19];
    const float* g_bz = (const float*)d_in[20];
    const float* d_W  = (const float*)d_in[21];
    const float* d_b  = (const float*)d_in[22];
    float* out = (float*)d_out;

    precompute_kernel<<<1, 512>>>(x_params, t_params, xW1, xb1, xW2, xb2,
                                  tW1, tb1, tW2, tb2, h0, gh0,
                                  f_Wh, f_bh, f_Wz, f_bz,
                                  g_Wh, g_bh, g_Wz, g_bz);

    cudaFuncSetAttribute(main_kernel, cudaFuncAttributeMaxDynamicSharedMemorySize,
                         SMEM_BYTES);
    main_kernel<<<NB * (NN / NITER), 256, SMEM_BYTES>>>(coords, f_Wz, d_W, d_b, out);
}

// round 6
// speedup vs baseline: 4.8176x; 1.3247x over previous
#include <cuda_runtime.h>
#include <cuda_bf16.h>
#include <cstdint>

#define DIMK 32
#define NBLK 6
#define NB   16
#define NN   256
#define NITER 4

// ---------------- global scratch ----------------
__device__ float    d_fbias[NBLK * NB * DIMK];
__device__ float    d_gbias[NBLK * NB * DIMK];
// B fragments (fp16, round-to-nearest) in exact mma.sync per-lane layout:
// units: 0..39   f blk1..5:  (blk-1)*8 + kt*4 + nt          (K=32, kt 0..1)
//        40..47  g blk0:     40 + kt*4 + nt                 (K=32, h part)
//        48..127 g blk1..5:  48 + (blk-1)*16 + kt*4 + nt    (K=64, kt 0..3)
__device__ uint32_t d_bfrag[128 * 64];

// ---------------- helpers ----------------
__device__ __forceinline__ uint32_t pack_f16x2(float lo, float hi) {
    uint32_t r;
    asm("cvt.rn.f16x2.f32 %0, %1, %2;" : "=r"(r) : "f"(hi), "f"(lo));
    return r;
}
__device__ __forceinline__ float2 unpack_f16x2(uint32_t u) {
    float2 f;
    asm("{ .reg .f16 l, h; mov.b32 {l, h}, %2; cvt.f32.f16 %0, l; cvt.f32.f16 %1, h; }"
        : "=f"(f.x), "=f"(f.y) : "r"(u));
    return f;
}
#define MMA16816(d, a, b) \
    asm volatile("mma.sync.aligned.m16n8k16.row.col.f32.f16.f16.f32 " \
        "{%0,%1,%2,%3}, {%4,%5,%6,%7}, {%8,%9}, {%0,%1,%2,%3};" \
        : "+f"((d)[0]), "+f"((d)[1]), "+f"((d)[2]), "+f"((d)[3]) \
        : "r"((a)[0]), "r"((a)[1]), "r"((a)[2]), "r"((a)[3]), \
          "r"((b)[0]), "r"((b)[1]))

// load 4 B units (8 regs) and run hi+lo A passes for both tt against them
#define CHUNK(ubase, A0h, A1h, A0l, A1l) do {                                    \
    uint32_t Bc[4][2];                                                           \
    _Pragma("unroll")                                                            \
    for (int nt = 0; nt < 4; nt++) {                                             \
        uint2 v = *(const uint2*)(s_bf + ((ubase) + nt) * 64 + lane * 2);        \
        Bc[nt][0] = v.x; Bc[nt][1] = v.y;                                        \
    }                                                                            \
    _Pragma("unroll")                                                            \
    for (int nt = 0; nt < 4; nt++) {                                             \
        MMA16816(acc[0][nt], (A0h), Bc[nt]);                                     \
        MMA16816(acc[1][nt], (A1h), Bc[nt]);                                     \
    }                                                                            \
    _Pragma("unroll")                                                            \
    for (int nt = 0; nt < 4; nt++) {                                             \
        MMA16816(acc[0][nt], (A0l), Bc[nt]);                                     \
        MMA16816(acc[1][nt], (A1l), Bc[nt]);                                     \
    }                                                                            \
} while (0)

// ---------------- precompute kernel ----------------
__global__ void precompute_kernel(
    const float* __restrict__ x_params, const float* __restrict__ t_params,
    const float* __restrict__ xW1, const float* __restrict__ xb1,
    const float* __restrict__ xW2, const float* __restrict__ xb2,
    const float* __restrict__ tW1, const float* __restrict__ tb1,
    const float* __restrict__ tW2, const float* __restrict__ tb2,
    const float* __restrict__ h0,  const float* __restrict__ gh0,
    const float* __restrict__ f_Wh, const float* __restrict__ f_bh,
    const float* __restrict__ f_Wz, const float* __restrict__ f_bz,
    const float* __restrict__ g_Wh, const float* __restrict__ g_bh,
    const float* __restrict__ g_Wz, const float* __restrict__ g_bz)
{
    __shared__ float s1x[NB][DIMK], s1t[NB][DIMK], ex[NB][DIMK], et[NB][DIMK];
    int t = threadIdx.x;  // 512 threads
    {
        int b = t / DIMK, k = t % DIMK;
        float a = xb1[k];
        for (int p = 0; p < 16; p++) a += x_params[b * 16 + p] * xW1[p * DIMK + k];
        s1x[b][k] = sinf(a);
        float c = tb1[k];
        for (int p = 0; p < 8; p++) c += t_params[b * 8 + p] * tW1[p * DIMK + k];
        s1t[b][k] = sinf(c);
    }
    __syncthreads();
    {
        int b = t / DIMK, k = t % DIMK;
        float a = xb2[k], c = tb2[k];
        for (int m = 0; m < DIMK; m++) {
            a += s1x[b][m] * xW2[m * DIMK + k];
            c += s1t[b][m] * tW2[m * DIMK + k];
        }
        ex[b][k] = a;
        et[b][k] = c;
    }
    __syncthreads();
    for (int idx = t; idx < NBLK * NB * DIMK; idx += blockDim.x) {
        int blk = idx / (NB * DIMK);
        int b   = (idx / DIMK) % NB;
        int k   = idx % DIMK;
        float fa = f_bh[blk * DIMK + k] + f_bz[blk * DIMK + k];
        for (int m = 0; m < DIMK; m++)
            fa += et[b][m] * f_Wz[(blk * 34 + 2 + m) * DIMK + k];
        if (blk == 0)
            for (int m = 0; m < DIMK; m++)
                fa += h0[m] * f_Wh[m * DIMK + k];
        d_fbias[idx] = fa;
        float ga = g_bh[blk * DIMK + k] + g_bz[blk * DIMK + k];
        for (int m = 0; m < DIMK; m++)
            ga += ex[b][m] * g_Wz[(blk * 64 + 32 + m) * DIMK + k];
        if (blk == 0)
            for (int m = 0; m < DIMK; m++)
                ga += gh0[m] * g_Wh[m * DIMK + k];
        d_gbias[idx] = ga;
    }
    // ---- B fragments (fp16 RN, per-lane mma layout) ----
    for (int e = t; e < 128 * 64; e += blockDim.x) {
        int u = e >> 6, r6 = e & 63, lane = r6 >> 1, reg = r6 & 1;
        int kt, nt, blk, isG;
        if (u < 40)      { blk = u / 8 + 1; int q = u % 8;  kt = q >> 2; nt = q & 3; isG = 0; }
        else if (u < 48) { int q = u - 40;  blk = 0;        kt = q >> 2; nt = q & 3; isG = 1; }
        else             { int q = u - 48;  blk = q / 16 + 1; q %= 16;   kt = q >> 2; nt = q & 3; isG = 1; }
        int k0 = kt * 16 + (lane & 3) * 2 + reg * 8;  // rows k0, k0+1
        int n  = nt * 8 + (lane >> 2);
        float w0, w1;
        if (!isG) {
            w0 = f_Wh[blk * 1024 + k0 * 32 + n];
            w1 = f_Wh[blk * 1024 + (k0 + 1) * 32 + n];
        } else if (blk == 0) {
            w0 = g_Wz[k0 * 32 + n];          // g blk0: h part rows 0..31
            w1 = g_Wz[(k0 + 1) * 32 + n];
        } else {
            w0 = (k0 < 32)     ? g_Wh[blk * 1024 + k0 * 32 + n]
                               : g_Wz[blk * 2048 + (k0 - 32) * 32 + n];
            int k1 = k0 + 1;
            w1 = (k1 < 32)     ? g_Wh[blk * 1024 + k1 * 32 + n]
                               : g_Wz[blk * 2048 + (k1 - 32) * 32 + n];
        }
        d_bfrag[e] = pack_f16x2(w0, w1);   // low half = smaller k
    }
}

// ---------------- smem layout ----------------
#define SM_BF_U32 (128 * 64)                      // 8192 u32 = 32 KB
#define SMEM_BYTES (32768 + (192 * 5 + 64) * 4)

// ---------------- main kernel ----------------
__global__ void __launch_bounds__(256, 2) main_kernel(
    const float* __restrict__ coords,  // (B,N,2)
    const float* __restrict__ f_Wz,    // (6,34,32)
    const float* __restrict__ d_W,     // (32)
    const float* __restrict__ d_b,     // (1)
    float* __restrict__ out)           // (B,N,N)
{
    extern __shared__ char smem[];
    uint32_t* s_bf  = (uint32_t*)smem;
    float*    s_fb  = (float*)(smem + 32768);
    float*    s_z0  = s_fb + 192;
    float*    s_z1  = s_z0 + 192;
    float*    s_gb  = s_z1 + 192;
    float*    s_fbt = s_gb + 192;
    float*    s_dW  = s_fbt + 192;   // 32

    const int tid = threadIdx.x;
    const int w   = tid >> 5;
    const int lane = tid & 31;
    const int t4  = lane >> 2;
    const int m4  = lane & 3;
    const int b   = blockIdx.x >> 6;
    const int i0  = (blockIdx.x & 63) * NITER;

    // ---- stage B fragments + per-batch vectors ----
    {
        const uint4* src = (const uint4*)d_bfrag;
        uint4* dst = (uint4*)s_bf;
        for (int idx = tid; idx < SM_BF_U32 / 4; idx += 256) dst[idx] = src[idx];
    }
    for (int idx = tid; idx < 192; idx += 256) {
        int blk = idx >> 5, k = idx & 31;
        s_fb[idx] = d_fbias[(blk * NB + b) * DIMK + k];
        s_gb[idx] = d_gbias[(blk * NB + b) * DIMK + k];
        s_z0[idx] = f_Wz[(blk * 34 + 0) * DIMK + k];
        s_z1[idx] = f_Wz[(blk * 34 + 1) * DIMK + k];
    }
    if (tid < 32) s_dW[tid] = d_W[tid];
    __syncthreads();

    const float dbv = d_b[0];

    // x for this warp's rows (j = column index of output grid, fixed across i)
    float xr[2][2];
#pragma unroll
    for (int tt = 0; tt < 2; tt++) {
        int j = (w * 2 + tt) * 16 + t4;
        xr[tt][0] = coords[(b * NN + j) * 2 + 0];
        xr[tt][1] = coords[(b * NN + j + 8) * 2 + 0];
    }

    uint32_t ahi[2][8], alo[2][8], hh[2][8], hl[2][8];
    float acc[2][4][4];

#pragma unroll 1
    for (int ii = 0; ii < NITER; ii++) {
        const int i = i0 + ii;
        const float tc = coords[(b * NN + i) * 2 + 1];
        __syncthreads();
        for (int idx = tid; idx < 192; idx += 256)
            s_fbt[idx] = s_fb[idx] + tc * s_z1[idx];
        __syncthreads();

        // ========== f blk0: h = sin(fbt + x*z0) ==========
#pragma unroll
        for (int tt = 0; tt < 2; tt++)
#pragma unroll
            for (int nt = 0; nt < 4; nt++) {
                int c = nt * 8 + m4 * 2;
                float2 fb2 = *(float2*)(s_fbt + c);
                float2 z02 = *(float2*)(s_z0 + c);
                float s0 = __sinf(fb2.x + xr[tt][0] * z02.x);
                float s1 = __sinf(fb2.y + xr[tt][0] * z02.y);
                float s2 = __sinf(fb2.x + xr[tt][1] * z02.x);
                float s3 = __sinf(fb2.y + xr[tt][1] * z02.y);
                int kt = nt >> 1, sl = (nt & 1) * 2;
                uint32_t p01 = pack_f16x2(s0, s1);
                uint32_t p23 = pack_f16x2(s2, s3);
                ahi[tt][kt * 4 + sl]     = p01;
                ahi[tt][kt * 4 + sl + 1] = p23;
                float2 r01 = unpack_f16x2(p01), r23 = unpack_f16x2(p23);
                alo[tt][kt * 4 + sl]     = pack_f16x2(s0 - r01.x, s1 - r01.y);
                alo[tt][kt * 4 + sl + 1] = pack_f16x2(s2 - r23.x, s3 - r23.y);
            }

        // ========== f blks 1..5 (K=32, A = h-prev) ==========
#pragma unroll 1
        for (int blk = 1; blk < NBLK; blk++) {
            const int ub = (blk - 1) * 8;
#pragma unroll
            for (int tt = 0; tt < 2; tt++)
#pragma unroll
                for (int nt = 0; nt < 4; nt++)
#pragma unroll
                    for (int q = 0; q < 4; q++) acc[tt][nt][q] = 0.0f;
#pragma unroll
            for (int kt = 0; kt < 2; kt++)
                CHUNK(ub + kt * 4, &ahi[0][kt * 4], &ahi[1][kt * 4],
                      &alo[0][kt * 4], &alo[1][kt * 4]);
            // epilogue + rebuild
#pragma unroll
            for (int tt = 0; tt < 2; tt++)
#pragma unroll
                for (int nt = 0; nt < 4; nt++) {
                    int c = nt * 8 + m4 * 2;
                    float2 fb2 = *(float2*)(s_fbt + blk * 32 + c);
                    float2 z02 = *(float2*)(s_z0 + blk * 32 + c);
                    float s0 = __sinf(acc[tt][nt][0] + fb2.x + xr[tt][0] * z02.x);
                    float s1 = __sinf(acc[tt][nt][1] + fb2.y + xr[tt][0] * z02.y);
                    float s2 = __sinf(acc[tt][nt][2] + fb2.x + xr[tt][1] * z02.x);
                    float s3 = __sinf(acc[tt][nt][3] + fb2.y + xr[tt][1] * z02.y);
                    int kt = nt >> 1, sl = (nt & 1) * 2;
                    uint32_t p01 = pack_f16x2(s0, s1);
                    uint32_t p23 = pack_f16x2(s2, s3);
                    ahi[tt][kt * 4 + sl]     = p01;
                    ahi[tt][kt * 4 + sl + 1] = p23;
                    float2 r01 = unpack_f16x2(p01), r23 = unpack_f16x2(p23);
                    alo[tt][kt * 4 + sl]     = pack_f16x2(s0 - r01.x, s1 - r01.y);
                    alo[tt][kt * 4 + sl + 1] = pack_f16x2(s2 - r23.x, s3 - r23.y);
                }
        }

        // keep h fragments for the g chain
#pragma unroll
        for (int tt = 0; tt < 2; tt++)
#pragma unroll
            for (int q = 0; q < 8; q++) { hh[tt][q] = ahi[tt][q]; hl[tt][q] = alo[tt][q]; }

        // ========== g blk0 (K=32, A = h) ==========
        {
#pragma unroll
            for (int tt = 0; tt < 2; tt++)
#pragma unroll
                for (int nt = 0; nt < 4; nt++)
#pragma unroll
                    for (int q = 0; q < 4; q++) acc[tt][nt][q] = 0.0f;
#pragma unroll
            for (int kt = 0; kt < 2; kt++)
                CHUNK(40 + kt * 4, &hh[0][kt * 4], &hh[1][kt * 4],
                      &hl[0][kt * 4], &hl[1][kt * 4]);
#pragma unroll
            for (int tt = 0; tt < 2; tt++)
#pragma unroll
                for (int nt = 0; nt < 4; nt++) {
                    int c = nt * 8 + m4 * 2;
                    float2 gb2 = *(float2*)(s_gb + c);
                    float s0 = __sinf(acc[tt][nt][0] + gb2.x);
                    float s1 = __sinf(acc[tt][nt][1] + gb2.y);
                    float s2 = __sinf(acc[tt][nt][2] + gb2.x);
                    float s3 = __sinf(acc[tt][nt][3] + gb2.y);
                    int kt = nt >> 1, sl = (nt & 1) * 2;
                    uint32_t p01 = pack_f16x2(s0, s1);
                    uint32_t p23 = pack_f16x2(s2, s3);
                    ahi[tt][kt * 4 + sl]     = p01;
                    ahi[tt][kt * 4 + sl + 1] = p23;
                    float2 r01 = unpack_f16x2(p01), r23 = unpack_f16x2(p23);
                    alo[tt][kt * 4 + sl]     = pack_f16x2(s0 - r01.x, s1 - r01.y);
                    alo[tt][kt * 4 + sl + 1] = pack_f16x2(s2 - r23.x, s3 - r23.y);
                }
        }

        // ========== g blks 1..5 (K=64: A = [gh ; h]) ==========
        float p0[2], p1[2];
#pragma unroll
        for (int tt = 0; tt < 2; tt++) { p0[tt] = 0.0f; p1[tt] = 0.0f; }

#pragma unroll 1
        for (int blk = 1; blk < NBLK; blk++) {
            const int ub = 48 + (blk - 1) * 16;
#pragma unroll
            for (int tt = 0; tt < 2; tt++)
#pragma unroll
                for (int nt = 0; nt < 4; nt++)
#pragma unroll
                    for (int q = 0; q < 4; q++) acc[tt][nt][q] = 0.0f;
            // kt 0,1: gh part; kt 2,3: h part
#pragma unroll
            for (int kt = 0; kt < 2; kt++)
                CHUNK(ub + kt * 4, &ahi[0][kt * 4], &ahi[1][kt * 4],
                      &alo[0][kt * 4], &alo[1][kt * 4]);
#pragma unroll
            for (int kt = 0; kt < 2; kt++)
                CHUNK(ub + 8 + kt * 4, &hh[0][kt * 4], &hh[1][kt * 4],
                      &hl[0][kt * 4], &hl[1][kt * 4]);

            const bool last = (blk == NBLK - 1);
#pragma unroll
            for (int tt = 0; tt < 2; tt++)
#pragma unroll
                for (int nt = 0; nt < 4; nt++) {
                    int c = nt * 8 + m4 * 2;
                    float2 gb2 = *(float2*)(s_gb + blk * 32 + c);
                    float s0 = __sinf(acc[tt][nt][0] + gb2.x);
                    float s1 = __sinf(acc[tt][nt][1] + gb2.y);
                    float s2 = __sinf(acc[tt][nt][2] + gb2.x);
                    float s3 = __sinf(acc[tt][nt][3] + gb2.y);
                    if (!last) {
                        int kt = nt >> 1, sl = (nt & 1) * 2;
                        uint32_t p01 = pack_f16x2(s0, s1);
                        uint32_t p23 = pack_f16x2(s2, s3);
                        ahi[tt][kt * 4 + sl]     = p01;
                        ahi[tt][kt * 4 + sl + 1] = p23;
                        float2 r01 = unpack_f16x2(p01), r23 = unpack_f16x2(p23);
                        alo[tt][kt * 4 + sl]     = pack_f16x2(s0 - r01.x, s1 - r01.y);
                        alo[tt][kt * 4 + sl + 1] = pack_f16x2(s2 - r23.x, s3 - r23.y);
                    } else {
                        float2 dw2 = *(float2*)(s_dW + c);
                        p0[tt] += s0 * dw2.x + s1 * dw2.y;
                        p1[tt] += s2 * dw2.x + s3 * dw2.y;
                    }
                }
        }

        // ========== decode reduce + store ==========
#pragma unroll
        for (int tt = 0; tt < 2; tt++) {
            p0[tt] += __shfl_xor_sync(0xffffffffu, p0[tt], 1);
            p0[tt] += __shfl_xor_sync(0xffffffffu, p0[tt], 2);
            p1[tt] += __shfl_xor_sync(0xffffffffu, p1[tt], 1);
            p1[tt] += __shfl_xor_sync(0xffffffffu, p1[tt], 2);
            if (m4 == 0) {
                int r0 = (w * 2 + tt) * 16 + t4;
                out[b * (NN * NN) + i * NN + r0]     = p0[tt] + dbv;
                out[b * (NN * NN) + i * NN + r0 + 8] = p1[tt] + dbv;
            }
        }
    }
}

// ---------------- launch ----------------
extern "C" void kernel_launch(void* const* d_in, const int* in_sizes, int n_in,
                              void* d_out, int out_size) {
    const float* coords   = (const float*)d_in[0];
    const float* x_params = (const float*)d_in[1];
    const float* t_params = (const float*)d_in[2];
    const float* xW1 = (const float*)d_in[3];
    const float* xb1 = (const float*)d_in[4];
    const float* xW2 = (const float*)d_in[5];
    const float* xb2 = (const float*)d_in[6];
    const float* tW1 = (const float*)d_in[7];
    const float* tb1 = (const float*)d_in[8];
    const float* tW2 = (const float*)d_in[9];
    const float* tb2 = (const float*)d_in[10];
    const float* h0  = (const float*)d_in[11];
    const float* gh0 = (const float*)d_in[12];
    const float* f_Wh = (const float*)d_in[13];
    const float* f_bh = (const float*)d_in[14];
    const float* f_Wz = (const float*)d_in[15];
    const float* f_bz = (const float*)d_in[16];
    const float* g_Wh = (const float*)d_in[17];
    const float* g_bh = (const float*)d_in[18];
    const float* g_Wz = (const float*)d_in[19];
    const float* g_bz = (const float*)d_in[20];
    const float* d_W  = (const float*)d_in[21];
    const float* d_b  = (const float*)d_in[22];
    float* out = (float*)d_out;

    precompute_kernel<<<1, 512>>>(x_params, t_params, xW1, xb1, xW2, xb2,
                                  tW1, tb1, tW2, tb2, h0, gh0,
                                  f_Wh, f_bh, f_Wz, f_bz,
                                  g_Wh, g_bh, g_Wz, g_bz);

    cudaFuncSetAttribute(main_kernel, cudaFuncAttributeMaxDynamicSharedMemorySize,
                         SMEM_BYTES);
    main_kernel<<<NB * (NN / NITER), 256, SMEM_BYTES>>>(coords, f_Wz, d_W, d_b, out);
}

// round 7
// speedup vs baseline: 6.5210x; 1.3536x over previous
#include <cuda_runtime.h>
#include <cuda_bf16.h>
#include <cstdint>

#define DIMK 32
#define NBLK 6
#define NB   16
#define NN   256
#define NITER 4

// ---------------- global scratch ----------------
__device__ float    d_fbias[NBLK * NB * DIMK];
__device__ float    d_gbias[NBLK * NB * DIMK];
// B fragments (fp16, round-to-nearest) in exact mma.sync per-lane layout:
// units: 0..39   f blk1..5:  (blk-1)*8 + kt*4 + nt          (K=32, kt 0..1)
//        40..47  g blk0:     40 + kt*4 + nt                 (K=32, h part)
//        48..127 g blk1..5:  48 + (blk-1)*16 + kt*4 + nt    (K=64, kt 0..3)
__device__ uint32_t d_bfrag[128 * 64];

// ---------------- helpers ----------------
__device__ __forceinline__ uint32_t pack_f16x2(float lo, float hi) {
    uint32_t r;
    asm("cvt.rn.f16x2.f32 %0, %1, %2;" : "=r"(r) : "f"(hi), "f"(lo));
    return r;
}
__device__ __forceinline__ float2 unpack_f16x2(uint32_t u) {
    float2 f;
    asm("{ .reg .f16 l, h; mov.b32 {l, h}, %2; cvt.f32.f16 %0, l; cvt.f32.f16 %1, h; }"
        : "=f"(f.x), "=f"(f.y) : "r"(u));
    return f;
}
#define MMA16816(d, a, b) \
    asm volatile("mma.sync.aligned.m16n8k16.row.col.f32.f16.f16.f32 " \
        "{%0,%1,%2,%3}, {%4,%5,%6,%7}, {%8,%9}, {%0,%1,%2,%3};" \
        : "+f"((d)[0]), "+f"((d)[1]), "+f"((d)[2]), "+f"((d)[3]) \
        : "r"((a)[0]), "r"((a)[1]), "r"((a)[2]), "r"((a)[3]), \
          "r"((b)[0]), "r"((b)[1]))

// 1-pass chunk: load 4 B units, run single A pass for both tt
#define CHUNK1(ubase, A0, A1) do {                                               \
    uint32_t Bc[4][2];                                                           \
    _Pragma("unroll")                                                            \
    for (int nt = 0; nt < 4; nt++) {                                             \
        uint2 v = *(const uint2*)(s_bf + ((ubase) + nt) * 64 + lane * 2);        \
        Bc[nt][0] = v.x; Bc[nt][1] = v.y;                                        \
    }                                                                            \
    _Pragma("unroll")                                                            \
    for (int nt = 0; nt < 4; nt++) {                                             \
        MMA16816(acc[0][nt], (A0), Bc[nt]);                                      \
        MMA16816(acc[1][nt], (A1), Bc[nt]);                                      \
    }                                                                            \
} while (0)

// 2-pass chunk: hi + lo A passes (for A = h, whose error would be systematic)
#define CHUNK2(ubase, A0h, A1h, A0l, A1l) do {                                   \
    uint32_t Bc[4][2];                                                           \
    _Pragma("unroll")                                                            \
    for (int nt = 0; nt < 4; nt++) {                                             \
        uint2 v = *(const uint2*)(s_bf + ((ubase) + nt) * 64 + lane * 2);        \
        Bc[nt][0] = v.x; Bc[nt][1] = v.y;                                        \
    }                                                                            \
    _Pragma("unroll")                                                            \
    for (int nt = 0; nt < 4; nt++) {                                             \
        MMA16816(acc[0][nt], (A0h), Bc[nt]);                                     \
        MMA16816(acc[1][nt], (A1h), Bc[nt]);                                     \
    }                                                                            \
    _Pragma("unroll")                                                            \
    for (int nt = 0; nt < 4; nt++) {                                             \
        MMA16816(acc[0][nt], (A0l), Bc[nt]);                                     \
        MMA16816(acc[1][nt], (A1l), Bc[nt]);                                     \
    }                                                                            \
} while (0)

// ---------------- precompute kernel ----------------
__global__ void precompute_kernel(
    const float* __restrict__ x_params, const float* __restrict__ t_params,
    const float* __restrict__ xW1, const float* __restrict__ xb1,
    const float* __restrict__ xW2, const float* __restrict__ xb2,
    const float* __restrict__ tW1, const float* __restrict__ tb1,
    const float* __restrict__ tW2, const float* __restrict__ tb2,
    const float* __restrict__ h0,  const float* __restrict__ gh0,
    const float* __restrict__ f_Wh, const float* __restrict__ f_bh,
    const float* __restrict__ f_Wz, const float* __restrict__ f_bz,
    const float* __restrict__ g_Wh, const float* __restrict__ g_bh,
    const float* __restrict__ g_Wz, const float* __restrict__ g_bz)
{
    __shared__ float s1x[NB][DIMK], s1t[NB][DIMK], ex[NB][DIMK], et[NB][DIMK];
    int t = threadIdx.x;  // 512 threads
    {
        int b = t / DIMK, k = t % DIMK;
        float a = xb1[k];
        for (int p = 0; p < 16; p++) a += x_params[b * 16 + p] * xW1[p * DIMK + k];
        s1x[b][k] = sinf(a);
        float c = tb1[k];
        for (int p = 0; p < 8; p++) c += t_params[b * 8 + p] * tW1[p * DIMK + k];
        s1t[b][k] = sinf(c);
    }
    __syncthreads();
    {
        int b = t / DIMK, k = t % DIMK;
        float a = xb2[k], c = tb2[k];
        for (int m = 0; m < DIMK; m++) {
            a += s1x[b][m] * xW2[m * DIMK + k];
            c += s1t[b][m] * tW2[m * DIMK + k];
        }
        ex[b][k] = a;
        et[b][k] = c;
    }
    __syncthreads();
    for (int idx = t; idx < NBLK * NB * DIMK; idx += blockDim.x) {
        int blk = idx / (NB * DIMK);
        int b   = (idx / DIMK) % NB;
        int k   = idx % DIMK;
        float fa = f_bh[blk * DIMK + k] + f_bz[blk * DIMK + k];
        for (int m = 0; m < DIMK; m++)
            fa += et[b][m] * f_Wz[(blk * 34 + 2 + m) * DIMK + k];
        if (blk == 0)
            for (int m = 0; m < DIMK; m++)
                fa += h0[m] * f_Wh[m * DIMK + k];
        d_fbias[idx] = fa;
        float ga = g_bh[blk * DIMK + k] + g_bz[blk * DIMK + k];
        for (int m = 0; m < DIMK; m++)
            ga += ex[b][m] * g_Wz[(blk * 64 + 32 + m) * DIMK + k];
        if (blk == 0)
            for (int m = 0; m < DIMK; m++)
                ga += gh0[m] * g_Wh[m * DIMK + k];
        d_gbias[idx] = ga;
    }
    // ---- B fragments (fp16 RN, per-lane mma layout) ----
    for (int e = t; e < 128 * 64; e += blockDim.x) {
        int u = e >> 6, r6 = e & 63, lane = r6 >> 1, reg = r6 & 1;
        int kt, nt, blk, isG;
        if (u < 40)      { blk = u / 8 + 1; int q = u % 8;  kt = q >> 2; nt = q & 3; isG = 0; }
        else if (u < 48) { int q = u - 40;  blk = 0;        kt = q >> 2; nt = q & 3; isG = 1; }
        else             { int q = u - 48;  blk = q / 16 + 1; q %= 16;   kt = q >> 2; nt = q & 3; isG = 1; }
        int k0 = kt * 16 + (lane & 3) * 2 + reg * 8;  // rows k0, k0+1
        int n  = nt * 8 + (lane >> 2);
        float w0, w1;
        if (!isG) {
            w0 = f_Wh[blk * 1024 + k0 * 32 + n];
            w1 = f_Wh[blk * 1024 + (k0 + 1) * 32 + n];
        } else if (blk == 0) {
            w0 = g_Wz[k0 * 32 + n];          // g blk0: h part rows 0..31
            w1 = g_Wz[(k0 + 1) * 32 + n];
        } else {
            w0 = (k0 < 32)     ? g_Wh[blk * 1024 + k0 * 32 + n]
                               : g_Wz[blk * 2048 + (k0 - 32) * 32 + n];
            int k1 = k0 + 1;
            w1 = (k1 < 32)     ? g_Wh[blk * 1024 + k1 * 32 + n]
                               : g_Wz[blk * 2048 + (k1 - 32) * 32 + n];
        }
        d_bfrag[e] = pack_f16x2(w0, w1);   // low half = smaller k
    }
}

// ---------------- smem layout ----------------
#define SM_BF_U32 (128 * 64)                      // 8192 u32 = 32 KB
#define SMEM_BYTES (32768 + (192 * 5 + 64) * 4)

// ---------------- main kernel ----------------
__global__ void __launch_bounds__(256, 2) main_kernel(
    const float* __restrict__ coords,  // (B,N,2)
    const float* __restrict__ f_Wz,    // (6,34,32)
    const float* __restrict__ d_W,     // (32)
    const float* __restrict__ d_b,     // (1)
    float* __restrict__ out)           // (B,N,N)
{
    extern __shared__ char smem[];
    uint32_t* s_bf  = (uint32_t*)smem;
    float*    s_fb  = (float*)(smem + 32768);
    float*    s_z0  = s_fb + 192;
    float*    s_z1  = s_z0 + 192;
    float*    s_gb  = s_z1 + 192;
    float*    s_fbt = s_gb + 192;
    float*    s_dW  = s_fbt + 192;   // 32

    const int tid = threadIdx.x;
    const int w   = tid >> 5;
    const int lane = tid & 31;
    const int t4  = lane >> 2;
    const int m4  = lane & 3;
    const int b   = blockIdx.x >> 6;
    const int i0  = (blockIdx.x & 63) * NITER;

    // ---- stage B fragments + per-batch vectors ----
    {
        const uint4* src = (const uint4*)d_bfrag;
        uint4* dst = (uint4*)s_bf;
        for (int idx = tid; idx < SM_BF_U32 / 4; idx += 256) dst[idx] = src[idx];
    }
    for (int idx = tid; idx < 192; idx += 256) {
        int blk = idx >> 5, k = idx & 31;
        s_fb[idx] = d_fbias[(blk * NB + b) * DIMK + k];
        s_gb[idx] = d_gbias[(blk * NB + b) * DIMK + k];
        s_z0[idx] = f_Wz[(blk * 34 + 0) * DIMK + k];
        s_z1[idx] = f_Wz[(blk * 34 + 1) * DIMK + k];
    }
    if (tid < 32) s_dW[tid] = d_W[tid];
    __syncthreads();

    const float dbv = d_b[0];

    // x for this warp's rows (j = column index of output grid, fixed across i)
    float xr[2][2];
#pragma unroll
    for (int tt = 0; tt < 2; tt++) {
        int j = (w * 2 + tt) * 16 + t4;
        xr[tt][0] = coords[(b * NN + j) * 2 + 0];
        xr[tt][1] = coords[(b * NN + j + 8) * 2 + 0];
    }

    uint32_t ahi[2][8], hh[2][8], hl[2][8];
    float acc[2][4][4];

#pragma unroll 1
    for (int ii = 0; ii < NITER; ii++) {
        const int i = i0 + ii;
        const float tc = coords[(b * NN + i) * 2 + 1];
        __syncthreads();
        for (int idx = tid; idx < 192; idx += 256)
            s_fbt[idx] = s_fb[idx] + tc * s_z1[idx];
        __syncthreads();

        // ========== f blk0: h = sin(fbt + x*z0), hi-only pack ==========
#pragma unroll
        for (int tt = 0; tt < 2; tt++)
#pragma unroll
            for (int nt = 0; nt < 4; nt++) {
                int c = nt * 8 + m4 * 2;
                float2 fb2 = *(float2*)(s_fbt + c);
                float2 z02 = *(float2*)(s_z0 + c);
                float s0 = __sinf(fb2.x + xr[tt][0] * z02.x);
                float s1 = __sinf(fb2.y + xr[tt][0] * z02.y);
                float s2 = __sinf(fb2.x + xr[tt][1] * z02.x);
                float s3 = __sinf(fb2.y + xr[tt][1] * z02.y);
                int kt = nt >> 1, sl = (nt & 1) * 2;
                ahi[tt][kt * 4 + sl]     = pack_f16x2(s0, s1);
                ahi[tt][kt * 4 + sl + 1] = pack_f16x2(s2, s3);
            }

        // ========== f blks 1..5 (K=32, 1-pass, acc preloaded with bias) ==========
#pragma unroll 1
        for (int blk = 1; blk < NBLK; blk++) {
            const int ub = (blk - 1) * 8;
            const bool lastf = (blk == NBLK - 1);
            // init acc with bias terms (off the post-MMA critical path)
#pragma unroll
            for (int tt = 0; tt < 2; tt++)
#pragma unroll
                for (int nt = 0; nt < 4; nt++) {
                    int c = nt * 8 + m4 * 2;
                    float2 fb2 = *(float2*)(s_fbt + blk * 32 + c);
                    float2 z02 = *(float2*)(s_z0 + blk * 32 + c);
                    acc[tt][nt][0] = fmaf(xr[tt][0], z02.x, fb2.x);
                    acc[tt][nt][1] = fmaf(xr[tt][0], z02.y, fb2.y);
                    acc[tt][nt][2] = fmaf(xr[tt][1], z02.x, fb2.x);
                    acc[tt][nt][3] = fmaf(xr[tt][1], z02.y, fb2.y);
                }
#pragma unroll
            for (int kt = 0; kt < 2; kt++)
                CHUNK1(ub + kt * 4, &ahi[0][kt * 4], &ahi[1][kt * 4]);
            // epilogue: sin + repack
#pragma unroll
            for (int tt = 0; tt < 2; tt++)
#pragma unroll
                for (int nt = 0; nt < 4; nt++) {
                    float s0 = __sinf(acc[tt][nt][0]);
                    float s1 = __sinf(acc[tt][nt][1]);
                    float s2 = __sinf(acc[tt][nt][2]);
                    float s3 = __sinf(acc[tt][nt][3]);
                    int kt = nt >> 1, sl = (nt & 1) * 2;
                    uint32_t p01 = pack_f16x2(s0, s1);
                    uint32_t p23 = pack_f16x2(s2, s3);
                    if (!lastf) {
                        ahi[tt][kt * 4 + sl]     = p01;
                        ahi[tt][kt * 4 + sl + 1] = p23;
                    } else {
                        // f output h: keep hi/lo split (feeds all 6 g layers)
                        hh[tt][kt * 4 + sl]     = p01;
                        hh[tt][kt * 4 + sl + 1] = p23;
                        float2 r01 = unpack_f16x2(p01), r23 = unpack_f16x2(p23);
                        hl[tt][kt * 4 + sl]     = pack_f16x2(s0 - r01.x, s1 - r01.y);
                        hl[tt][kt * 4 + sl + 1] = pack_f16x2(s2 - r23.x, s3 - r23.y);
                    }
                }
        }

        // ========== g blk0 (K=32, A = h, 2-pass) ==========
        {
#pragma unroll
            for (int tt = 0; tt < 2; tt++)
#pragma unroll
                for (int nt = 0; nt < 4; nt++) {
                    int c = nt * 8 + m4 * 2;
                    float2 gb2 = *(float2*)(s_gb + c);
                    acc[tt][nt][0] = gb2.x;
                    acc[tt][nt][1] = gb2.y;
                    acc[tt][nt][2] = gb2.x;
                    acc[tt][nt][3] = gb2.y;
                }
#pragma unroll
            for (int kt = 0; kt < 2; kt++)
                CHUNK2(40 + kt * 4, &hh[0][kt * 4], &hh[1][kt * 4],
                       &hl[0][kt * 4], &hl[1][kt * 4]);
#pragma unroll
            for (int tt = 0; tt < 2; tt++)
#pragma unroll
                for (int nt = 0; nt < 4; nt++) {
                    float s0 = __sinf(acc[tt][nt][0]);
                    float s1 = __sinf(acc[tt][nt][1]);
                    float s2 = __sinf(acc[tt][nt][2]);
                    float s3 = __sinf(acc[tt][nt][3]);
                    int kt = nt >> 1, sl = (nt & 1) * 2;
                    ahi[tt][kt * 4 + sl]     = pack_f16x2(s0, s1);
                    ahi[tt][kt * 4 + sl + 1] = pack_f16x2(s2, s3);
                }
        }

        // ========== g blks 1..5 (K=64: gh 1-pass + h 2-pass) ==========
        float p0[2], p1[2];
#pragma unroll
        for (int tt = 0; tt < 2; tt++) { p0[tt] = 0.0f; p1[tt] = 0.0f; }

#pragma unroll 1
        for (int blk = 1; blk < NBLK; blk++) {
            const int ub = 48 + (blk - 1) * 16;
#pragma unroll
            for (int tt = 0; tt < 2; tt++)
#pragma unroll
                for (int nt = 0; nt < 4; nt++) {
                    int c = nt * 8 + m4 * 2;
                    float2 gb2 = *(float2*)(s_gb + blk * 32 + c);
                    acc[tt][nt][0] = gb2.x;
                    acc[tt][nt][1] = gb2.y;
                    acc[tt][nt][2] = gb2.x;
                    acc[tt][nt][3] = gb2.y;
                }
            // kt 0,1: gh part (1-pass); kt 2,3 (ub+8..): h part (2-pass)
#pragma unroll
            for (int kt = 0; kt < 2; kt++)
                CHUNK1(ub + kt * 4, &ahi[0][kt * 4], &ahi[1][kt * 4]);
#pragma unroll
            for (int kt = 0; kt < 2; kt++)
                CHUNK2(ub + 8 + kt * 4, &hh[0][kt * 4], &hh[1][kt * 4],
                       &hl[0][kt * 4], &hl[1][kt * 4]);

            const bool last = (blk == NBLK - 1);
#pragma unroll
            for (int tt = 0; tt < 2; tt++)
#pragma unroll
                for (int nt = 0; nt < 4; nt++) {
                    float s0 = __sinf(acc[tt][nt][0]);
                    float s1 = __sinf(acc[tt][nt][1]);
                    float s2 = __sinf(acc[tt][nt][2]);
                    float s3 = __sinf(acc[tt][nt][3]);
                    if (!last) {
                        int kt = nt >> 1, sl = (nt & 1) * 2;
                        ahi[tt][kt * 4 + sl]     = pack_f16x2(s0, s1);
                        ahi[tt][kt * 4 + sl + 1] = pack_f16x2(s2, s3);
                    } else {
                        int c = nt * 8 + m4 * 2;
                        float2 dw2 = *(float2*)(s_dW + c);
                        p0[tt] += s0 * dw2.x + s1 * dw2.y;
                        p1[tt] += s2 * dw2.x + s3 * dw2.y;
                    }
                }
        }

        // ========== decode reduce + store ==========
#pragma unroll
        for (int tt = 0; tt < 2; tt++) {
            p0[tt] += __shfl_xor_sync(0xffffffffu, p0[tt], 1);
            p0[tt] += __shfl_xor_sync(0xffffffffu, p0[tt], 2);
            p1[tt] += __shfl_xor_sync(0xffffffffu, p1[tt], 1);
            p1[tt] += __shfl_xor_sync(0xffffffffu, p1[tt], 2);
            if (m4 == 0) {
                int r0 = (w * 2 + tt) * 16 + t4;
                out[b * (NN * NN) + i * NN + r0]     = p0[tt] + dbv;
                out[b * (NN * NN) + i * NN + r0 + 8] = p1[tt] + dbv;
            }
        }
    }
}

// ---------------- launch ----------------
extern "C" void kernel_launch(void* const* d_in, const int* in_sizes, int n_in,
                              void* d_out, int out_size) {
    const float* coords   = (const float*)d_in[0];
    const float* x_params = (const float*)d_in[1];
    const float* t_params = (const float*)d_in[2];
    const float* xW1 = (const float*)d_in[3];
    const float* xb1 = (const float*)d_in[4];
    const float* xW2 = (const float*)d_in[5];
    const float* xb2 = (const float*)d_in[6];
    const float* tW1 = (const float*)d_in[7];
    const float* tb1 = (const float*)d_in[8];
    const float* tW2 = (const float*)d_in[9];
    const float* tb2 = (const float*)d_in[10];
    const float* h0  = (const float*)d_in[11];
    const float* gh0 = (const float*)d_in[12];
    const float* f_Wh = (const float*)d_in[13];
    const float* f_bh = (const float*)d_in[14];
    const float* f_Wz = (const float*)d_in[15];
    const float* f_bz = (const float*)d_in[16];
    const float* g_Wh = (const float*)d_in[17];
    const float* g_bh = (const float*)d_in[18];
    const float* g_Wz = (const float*)d_in[19];
    const float* g_bz = (const float*)d_in[20];
    const float* d_W  = (const float*)d_in[21];
    const float* d_b  = (const float*)d_in[22];
    float* out = (float*)d_out;

    precompute_kernel<<<1, 512>>>(x_params, t_params, xW1, xb1, xW2, xb2,
                                  tW1, tb1, tW2, tb2, h0, gh0,
                                  f_Wh, f_bh, f_Wz, f_bz,
                                  g_Wh, g_bh, g_Wz, g_bz);

    cudaFuncSetAttribute(main_kernel, cudaFuncAttributeMaxDynamicSharedMemorySize,
                         SMEM_BYTES);
    main_kernel<<<NB * (NN / NITER), 256, SMEM_BYTES>>>(coords, f_Wz, d_W, d_b, out);
}